// round 1
// baseline (speedup 1.0000x reference)
#include <cuda_runtime.h>
#include <cstdint>

#define Bsz   2048
#define Lseq  256
#define Hdim  64
#define Gdim  256   // 4*H
#define Edim  64
#define VOC   128
#define BT    32    // batch tile per block

// ---------------- device scratch (no cudaMalloc allowed) ----------------
__device__ float g_T0[2 * VOC * Gdim];                 // 256 KB  token tables (layer0 input proj + biases)
__device__ float g_y0[(size_t)Lseq * Bsz * 128];       // 268 MB  layer-0 output [t][b][128] (fwd 0:64, bwd 64:128)
__device__ float g_hfin[Bsz * 128];                    // 1 MB    layer-1 final hidden [b][hf|hb]

// ---------------- fast activations (EX2 + RCP, ~1e-6 rel err) ----------------
__device__ __forceinline__ float sigf(float x) {
    return __fdividef(1.f, 1.f + __expf(-x));
}
__device__ __forceinline__ float tanhf_(float x) {
    return 2.f * sigf(2.f * x) - 1.f;
}

// ---------------- kernel 1: layer-0 token tables ----------------
// T0[dir][v][g] = sum_k emb[v][k]*Wih0[dir][g][k] + b0[dir][0][g] + b0[dir][1][g]
__global__ void table_kernel(const float* __restrict__ emb,
                             const float* __restrict__ Wih0,
                             const float* __restrict__ b0) {
    int v = blockIdx.x, dir = blockIdx.y, g = threadIdx.x;   // 256 threads
    __shared__ float se[Edim];
    if (g < Edim) se[g] = emb[v * Edim + g];
    __syncthreads();
    const float* w = Wih0 + (dir * Gdim + g) * Edim;
    float s = b0[dir * 2 * Gdim + g] + b0[dir * 2 * Gdim + Gdim + g];
#pragma unroll
    for (int k = 0; k < Edim; k++) s += se[k] * w[k];
    g_T0[(dir * VOC + v) * Gdim + g] = s;
}

// ---------------- kernel 2: layer-0 bidirectional recurrence ----------------
// grid (64, 2): blockIdx.x = batch tile, blockIdx.y = direction
// block 256 threads: ty=tid>>5 owns batches ty*4..ty*4+3, tx=tid&31 owns gate cols {2tx+c+64q}
__global__ void __launch_bounds__(256, 1)
lstm0_kernel(const int* __restrict__ x, const float* __restrict__ Whh0) {
    extern __shared__ float smem[];
    float* sWT = smem;              // [64][256]  W^T (k-major)
    float* sh  = smem + 64 * 256;   // [32][64]   h state

    const int dir = blockIdx.y;
    const int b0i = blockIdx.x * BT;
    const int tid = threadIdx.x, tx = tid & 31, ty = tid >> 5;

    // transpose Whh into smem (k-major): thread owns column g=tid
    const float* W = Whh0 + dir * Gdim * Hdim;
#pragma unroll 8
    for (int k = 0; k < Hdim; k++) sWT[k * Gdim + tid] = W[tid * Hdim + k];
    for (int i = tid; i < BT * Hdim; i += 256) sh[i] = 0.f;
    __syncthreads();

    float cst[4][2];
#pragma unroll
    for (int bi = 0; bi < 4; bi++) { cst[bi][0] = 0.f; cst[bi][1] = 0.f; }

    const float* T0 = g_T0 + dir * VOC * Gdim;

    for (int t = 0; t < Lseq; t++) {
        const int tcur = dir ? (Lseq - 1 - t) : t;

        // acc init = precomputed input projection (table row gather, L1/L2-hot)
        float acc[4][2][4];
#pragma unroll
        for (int bi = 0; bi < 4; bi++) {
            int b = b0i + ty * 4 + bi;
            int tok = __ldg(&x[b * Lseq + tcur]);
            const float* row = T0 + tok * Gdim;
#pragma unroll
            for (int q = 0; q < 4; q++) {
                float2 v = *(const float2*)(row + q * 64 + 2 * tx);
                acc[bi][0][q] = v.x; acc[bi][1][q] = v.y;
            }
        }
        __syncthreads();   // prev h writes visible before reading sh

        // gates += h @ Whh^T  (K = 64)
#pragma unroll 4
        for (int k = 0; k < Hdim; k++) {
            float2 w0 = *(const float2*)&sWT[k * Gdim +   0 + 2 * tx];
            float2 w1 = *(const float2*)&sWT[k * Gdim +  64 + 2 * tx];
            float2 w2 = *(const float2*)&sWT[k * Gdim + 128 + 2 * tx];
            float2 w3 = *(const float2*)&sWT[k * Gdim + 192 + 2 * tx];
#pragma unroll
            for (int bi = 0; bi < 4; bi++) {
                float hv = sh[(ty * 4 + bi) * Hdim + k];
                acc[bi][0][0] += hv * w0.x; acc[bi][1][0] += hv * w0.y;
                acc[bi][0][1] += hv * w1.x; acc[bi][1][1] += hv * w1.y;
                acc[bi][0][2] += hv * w2.x; acc[bi][1][2] += hv * w2.y;
                acc[bi][0][3] += hv * w3.x; acc[bi][1][3] += hv * w3.y;
            }
        }
        __syncthreads();   // all k-loop reads of sh done before overwriting

        // gate nonlinearities (all 4 gates of a cell live in this thread)
#pragma unroll
        for (int bi = 0; bi < 4; bi++) {
            int b = b0i + ty * 4 + bi;
            float2 hp;
#pragma unroll
            for (int c = 0; c < 2; c++) {
                float i_ = sigf(acc[bi][c][0]);
                float f_ = sigf(acc[bi][c][1]);
                float g_ = tanhf_(acc[bi][c][2]);
                float o_ = sigf(acc[bi][c][3]);
                float cn = f_ * cst[bi][c] + i_ * g_;
                cst[bi][c] = cn;
                float hv = o_ * tanhf_(cn);
                if (c == 0) hp.x = hv; else hp.y = hv;
            }
            *(float2*)&sh[(ty * 4 + bi) * Hdim + 2 * tx] = hp;
            *(float2*)&g_y0[((size_t)tcur * Bsz + b) * 128 + dir * 64 + 2 * tx] = hp;
        }
    }
}

// ---------------- kernel 3: layer-1 recurrence with fused input projection ----------------
// gates = bias + [y0(128) | h(64)] @ [Wih1 ; Whh1]^T   (K = 192)
__global__ void __launch_bounds__(256, 1)
lstm1_kernel(const float* __restrict__ Wih1, const float* __restrict__ Whh1,
             const float* __restrict__ b1) {
    extern __shared__ float smem[];
    float* sWT = smem;               // [192][256] combined W^T (k-major)  192 KB
    float* sY  = smem + 192 * 256;   // [32][192]  cols 0:128 = y tile, 128:192 = h   24 KB

    const int dir = blockIdx.y;
    const int b0i = blockIdx.x * BT;
    const int tid = threadIdx.x, tx = tid & 31, ty = tid >> 5;

    // fill combined transposed weights: thread owns column g=tid
    {
        const float* Wi = Wih1 + dir * Gdim * 128;
        const float* Wh = Whh1 + dir * Gdim * Hdim;
        for (int k = 0; k < 128; k++)  sWT[k * Gdim + tid] = Wi[tid * 128 + k];
        for (int k = 0; k < Hdim; k++) sWT[(128 + k) * Gdim + tid] = Wh[tid * Hdim + k];
    }
    // zero h region
    for (int i = tid; i < BT * Hdim; i += 256) {
        int b = i >> 6, j = i & 63;
        sY[b * 192 + 128 + j] = 0.f;
    }
    // per-thread gate biases
    float bias[2][4];
#pragma unroll
    for (int q = 0; q < 4; q++)
#pragma unroll
        for (int c = 0; c < 2; c++) {
            int g = 2 * tx + c + 64 * q;
            bias[c][q] = b1[dir * 2 * Gdim + g] + b1[dir * 2 * Gdim + Gdim + g];
        }
    __syncthreads();

    float cst[4][2];
#pragma unroll
    for (int bi = 0; bi < 4; bi++) { cst[bi][0] = 0.f; cst[bi][1] = 0.f; }

    for (int t = 0; t < Lseq; t++) {
        const int tcur = dir ? (Lseq - 1 - t) : t;

        // stage y0 tile [32][128] (16 KB, fully coalesced)
        const float4* ysrc = (const float4*)(g_y0 + ((size_t)tcur * Bsz + b0i) * 128);
        for (int i = tid; i < (BT * 128) / 4; i += 256) {
            float4 v = ysrc[i];
            int e = i * 4, b = e >> 7, f = e & 127;
            *(float4*)&sY[b * 192 + f] = v;
        }

        float acc[4][2][4];
#pragma unroll
        for (int bi = 0; bi < 4; bi++)
#pragma unroll
            for (int c = 0; c < 2; c++)
#pragma unroll
                for (int q = 0; q < 4; q++) acc[bi][c][q] = bias[c][q];

        __syncthreads();   // y tile + prev h visible

#pragma unroll 4
        for (int k = 0; k < 192; k++) {
            float2 w0 = *(const float2*)&sWT[k * Gdim +   0 + 2 * tx];
            float2 w1 = *(const float2*)&sWT[k * Gdim +  64 + 2 * tx];
            float2 w2 = *(const float2*)&sWT[k * Gdim + 128 + 2 * tx];
            float2 w3 = *(const float2*)&sWT[k * Gdim + 192 + 2 * tx];
#pragma unroll
            for (int bi = 0; bi < 4; bi++) {
                float hv = sY[(ty * 4 + bi) * 192 + k];
                acc[bi][0][0] += hv * w0.x; acc[bi][1][0] += hv * w0.y;
                acc[bi][0][1] += hv * w1.x; acc[bi][1][1] += hv * w1.y;
                acc[bi][0][2] += hv * w2.x; acc[bi][1][2] += hv * w2.y;
                acc[bi][0][3] += hv * w3.x; acc[bi][1][3] += hv * w3.y;
            }
        }
        __syncthreads();   // k-loop done before h overwrite (y overwrite is next iter, after this barrier too)

#pragma unroll
        for (int bi = 0; bi < 4; bi++) {
            int b = b0i + ty * 4 + bi;
            float2 hp;
#pragma unroll
            for (int c = 0; c < 2; c++) {
                float i_ = sigf(acc[bi][c][0]);
                float f_ = sigf(acc[bi][c][1]);
                float g_ = tanhf_(acc[bi][c][2]);
                float o_ = sigf(acc[bi][c][3]);
                float cn = f_ * cst[bi][c] + i_ * g_;
                cst[bi][c] = cn;
                float hv = o_ * tanhf_(cn);
                if (c == 0) hp.x = hv; else hp.y = hv;
            }
            *(float2*)&sY[(ty * 4 + bi) * 192 + 128 + 2 * tx] = hp;
            if (t == Lseq - 1)
                *(float2*)&g_hfin[b * 128 + dir * 64 + 2 * tx] = hp;
        }
    }
}

// ---------------- kernel 4: MLP head ----------------
// out[b] = relu(hfin[b] @ W1^T + bf1) @ W2^T + bf2
__global__ void head_kernel(const float* __restrict__ W1, const float* __restrict__ bf1,
                            const float* __restrict__ W2, const float* __restrict__ bf2,
                            float* __restrict__ out) {
    int b = blockIdx.x, j = threadIdx.x;   // 64 threads
    __shared__ float shh[128];
    __shared__ float sred[2];
    shh[j]      = g_hfin[b * 128 + j];
    shh[j + 64] = g_hfin[b * 128 + 64 + j];
    __syncthreads();
    float z = bf1[j];
    const float* w = W1 + j * 128;
#pragma unroll 8
    for (int k = 0; k < 128; k++) z += shh[k] * w[k];
    z = fmaxf(z, 0.f) * W2[j];
#pragma unroll
    for (int o = 16; o; o >>= 1) z += __shfl_down_sync(0xffffffffu, z, o);
    if ((j & 31) == 0) sred[j >> 5] = z;
    __syncthreads();
    if (j == 0) out[b] = sred[0] + sred[1] + bf2[0];
}

// ---------------- launch ----------------
extern "C" void kernel_launch(void* const* d_in, const int* in_sizes, int n_in,
                              void* d_out, int out_size) {
    const int*   x    = (const int*)  d_in[0];
    const float* emb  = (const float*)d_in[1];
    const float* Wih0 = (const float*)d_in[2];
    const float* Whh0 = (const float*)d_in[3];
    const float* b0   = (const float*)d_in[4];
    const float* Wih1 = (const float*)d_in[5];
    const float* Whh1 = (const float*)d_in[6];
    const float* b1   = (const float*)d_in[7];
    const float* W1   = (const float*)d_in[8];
    const float* bf1  = (const float*)d_in[9];
    const float* W2   = (const float*)d_in[10];
    const float* bf2  = (const float*)d_in[11];
    float* out = (float*)d_out;

    const int SMEM0 = (64 * 256 + BT * 64) * 4;        // 73728
    const int SMEM1 = (192 * 256 + BT * 192) * 4;      // 221184
    cudaFuncSetAttribute(lstm0_kernel, cudaFuncAttributeMaxDynamicSharedMemorySize, SMEM0);
    cudaFuncSetAttribute(lstm1_kernel, cudaFuncAttributeMaxDynamicSharedMemorySize, SMEM1);

    table_kernel<<<dim3(VOC, 2), Gdim>>>(emb, Wih0, b0);
    lstm0_kernel<<<dim3(Bsz / BT, 2), 256, SMEM0>>>(x, Whh0);
    lstm1_kernel<<<dim3(Bsz / BT, 2), 256, SMEM1>>>(Wih1, Whh1, b1);
    head_kernel<<<Bsz, 64>>>(W1, bf1, W2, bf2, out);
}

// round 2
// speedup vs baseline: 1.5102x; 1.5102x over previous
#include <cuda_runtime.h>
#include <cstdint>

#define Bsz   2048
#define Lseq  256
#define Hdim  64
#define Gdim  256   // 4*H
#define Edim  64
#define VOC   128
#define BT    32    // batch tile per block
#define HSTRIDE 36  // padded row stride for transposed h/y smem

// ---------------- device scratch ----------------
__device__ float g_T0[2 * VOC * Gdim];                  // token tables (layer0 in-proj + biases)
__device__ float g_y0t[(size_t)Lseq * 128 * Bsz];       // layer-0 output TRANSPOSED [t][f][b]
__device__ float g_hfin[Bsz * 128];                     // layer-1 final hidden [b][hf|hb]

// ---------------- f32x2 + fast activation helpers ----------------
__device__ __forceinline__ unsigned long long pack2(float a, float b) {
    unsigned long long r;
    asm("mov.b64 %0, {%1,%2};" : "=l"(r) : "f"(a), "f"(b));
    return r;
}
__device__ __forceinline__ void unpack2(unsigned long long v, float& a, float& b) {
    asm("mov.b64 {%0,%1}, %2;" : "=f"(a), "=f"(b) : "l"(v));
}
__device__ __forceinline__ unsigned long long fma2(unsigned long long a, unsigned long long b,
                                                   unsigned long long c) {
    unsigned long long d;
    asm("fma.rn.f32x2 %0, %1, %2, %3;" : "=l"(d) : "l"(a), "l"(b), "l"(c));
    return d;
}
__device__ __forceinline__ float tanha(float x) {
    float y; asm("tanh.approx.f32 %0, %1;" : "=f"(y) : "f"(x)); return y;
}
__device__ __forceinline__ float sigf(float x) {       // sigmoid via HW tanh
    return fmaf(0.5f, tanha(0.5f * x), 0.5f);
}

// ---------------- kernel 1: layer-0 token tables ----------------
__global__ void table_kernel(const float* __restrict__ emb,
                             const float* __restrict__ Wih0,
                             const float* __restrict__ b0) {
    int v = blockIdx.x, dir = blockIdx.y, g = threadIdx.x;   // 256 threads
    __shared__ float se[Edim];
    if (g < Edim) se[g] = emb[v * Edim + g];
    __syncthreads();
    const float* w = Wih0 + (dir * Gdim + g) * Edim;
    float s = b0[dir * 2 * Gdim + g] + b0[dir * 2 * Gdim + Gdim + g];
#pragma unroll
    for (int k = 0; k < Edim; k++) s += se[k] * w[k];
    g_T0[(dir * VOC + v) * Gdim + g] = s;
}

// ---------------- kernel 2: layer-0 bidirectional recurrence ----------------
// warp w: ch = w&1 (cell half), bo = w>>1 (batch octet). lane l -> cell c = 32*ch + l.
// Each lane: 1 cell (4 gates) x 8 batches. acc = f32x2 pairs over batches.
__global__ void __launch_bounds__(256, 1)
lstm0_kernel(const int* __restrict__ x, const float* __restrict__ Whh0) {
    extern __shared__ float smem[];
    float* sW  = smem;                      // [64][64 cells][4 gates] = 64*256
    float* sHT = smem + Hdim * Gdim;        // [64][HSTRIDE] h transposed

    const int dir = blockIdx.y;
    const int b0i = blockIdx.x * BT;
    const int tid = threadIdx.x, lane = tid & 31, w = tid >> 5;
    const int ch = w & 1, bo = w >> 1;
    const int c = ch * 32 + lane;

    // weight fill: thread owns gate column g: sW[k][4*(g&63) + (g>>6)]
    {
        const float* W = Whh0 + (dir * Gdim + tid) * Hdim;
        const int idx = 4 * (tid & 63) + (tid >> 6);
        for (int k = 0; k < Hdim; k++) sW[k * Gdim + idx] = W[k];
    }
    for (int i = tid; i < Hdim * HSTRIDE; i += 256) sHT[i] = 0.f;
    __syncthreads();

    float cst[8];
#pragma unroll
    for (int j = 0; j < 8; j++) cst[j] = 0.f;

    const float* T0 = g_T0 + dir * VOC * Gdim;
    const float* wp0 = sW + 4 * c;
    const float* hp0 = sHT + 8 * bo;

    for (int t = 0; t < Lseq; t++) {
        const int tcur = dir ? (Lseq - 1 - t) : t;

        // acc init = token-table gather. pairs over batches.
        unsigned long long acc[4][4];
#pragma unroll
        for (int p = 0; p < 4; p++) {
            int bA = b0i + 8 * bo + 2 * p, bB = bA + 1;
            const float* rA = T0 + (size_t)__ldg(&x[bA * Lseq + tcur]) * Gdim;
            const float* rB = T0 + (size_t)__ldg(&x[bB * Lseq + tcur]) * Gdim;
#pragma unroll
            for (int q = 0; q < 4; q++)
                acc[q][p] = pack2(rA[q * 64 + c], rB[q * 64 + c]);
        }
        __syncthreads();   // h(t-1) visible

#pragma unroll 4
        for (int k = 0; k < Hdim; k++) {
            float4 wv = *(const float4*)(wp0 + k * Gdim);          // gates i,f,g,o of cell c
            unsigned long long w2[4];
            w2[0] = pack2(wv.x, wv.x); w2[1] = pack2(wv.y, wv.y);
            w2[2] = pack2(wv.z, wv.z); w2[3] = pack2(wv.w, wv.w);
            ulonglong2 hA = *(const ulonglong2*)(hp0 + k * HSTRIDE);      // batches 0-3 (2 pairs)
            ulonglong2 hB = *(const ulonglong2*)(hp0 + k * HSTRIDE + 4);  // batches 4-7
#pragma unroll
            for (int q = 0; q < 4; q++) {
                acc[q][0] = fma2(w2[q], hA.x, acc[q][0]);
                acc[q][1] = fma2(w2[q], hA.y, acc[q][1]);
                acc[q][2] = fma2(w2[q], hB.x, acc[q][2]);
                acc[q][3] = fma2(w2[q], hB.y, acc[q][3]);
            }
        }
        __syncthreads();   // reads done before h overwrite

        // gate math -> h (8 batches of cell c)
        float hv[8];
#pragma unroll
        for (int p = 0; p < 4; p++) {
            float i0, i1, f0, f1, g0, g1, o0, o1;
            unpack2(acc[0][p], i0, i1); unpack2(acc[1][p], f0, f1);
            unpack2(acc[2][p], g0, g1); unpack2(acc[3][p], o0, o1);
            float cn0 = sigf(f0) * cst[2 * p]     + sigf(i0) * tanha(g0);
            float cn1 = sigf(f1) * cst[2 * p + 1] + sigf(i1) * tanha(g1);
            cst[2 * p] = cn0; cst[2 * p + 1] = cn1;
            hv[2 * p]     = sigf(o0) * tanha(cn0);
            hv[2 * p + 1] = sigf(o1) * tanha(cn1);
        }
        float4 hA = make_float4(hv[0], hv[1], hv[2], hv[3]);
        float4 hB = make_float4(hv[4], hv[5], hv[6], hv[7]);
        *(float4*)(sHT + c * HSTRIDE + 8 * bo)     = hA;
        *(float4*)(sHT + c * HSTRIDE + 8 * bo + 4) = hB;
        float* yrow = g_y0t + ((size_t)tcur * 128 + dir * 64 + c) * Bsz + b0i + 8 * bo;
        *(float4*)yrow       = hA;
        *(float4*)(yrow + 4) = hB;
    }
}

// ---------------- kernel 3: layer-1 recurrence, fused input projection ----------------
// K = 192: rows 0..127 = y0 tile (staged per step, transposed), 128..191 = h.
__global__ void __launch_bounds__(256, 1)
lstm1_kernel(const float* __restrict__ Wih1, const float* __restrict__ Whh1,
             const float* __restrict__ b1) {
    extern __shared__ float smem[];
    float* sW  = smem;                       // [192][256] interleaved per cell
    float* sYT = smem + 192 * Gdim;          // [192][HSTRIDE]

    const int dir = blockIdx.y;
    const int b0i = blockIdx.x * BT;
    const int tid = threadIdx.x, lane = tid & 31, w = tid >> 5;
    const int ch = w & 1, bo = w >> 1;
    const int c = ch * 32 + lane;

    {
        const int idx = 4 * (tid & 63) + (tid >> 6);
        const float* Wi = Wih1 + (dir * Gdim + tid) * 128;
        const float* Wh = Whh1 + (dir * Gdim + tid) * Hdim;
        for (int k = 0; k < 128; k++)  sW[k * Gdim + idx] = Wi[k];
        for (int k = 0; k < Hdim; k++) sW[(128 + k) * Gdim + idx] = Wh[k];
    }
    for (int i = tid; i < 192 * HSTRIDE; i += 256) sYT[i] = 0.f;

    // per-lane gate biases (pair-packed, same both lanes)
    unsigned long long bias2[4];
#pragma unroll
    for (int q = 0; q < 4; q++) {
        int g = q * 64 + c;
        float b = b1[dir * 2 * Gdim + g] + b1[dir * 2 * Gdim + Gdim + g];
        bias2[q] = pack2(b, b);
    }
    __syncthreads();

    float cst[8];
#pragma unroll
    for (int j = 0; j < 8; j++) cst[j] = 0.f;

    const float* wp0 = sW + 4 * c;
    const float* hp0 = sYT + 8 * bo;
    const int sr = tid >> 1, sc0 = 16 * (tid & 1);   // staging: 2 threads per f-row

    for (int t = 0; t < Lseq; t++) {
        const int tcur = dir ? (Lseq - 1 - t) : t;

        // stage y0(t) transposed tile: rows 0..127, cols 0..31
        {
            const float* ysrc = g_y0t + ((size_t)tcur * 128) * Bsz + b0i;
#pragma unroll
            for (int u = 0; u < 4; u++) {
                float4 v = *(const float4*)(ysrc + (size_t)sr * Bsz + sc0 + 4 * u);
                *(float4*)(sYT + sr * HSTRIDE + sc0 + 4 * u) = v;
            }
        }

        unsigned long long acc[4][4];
#pragma unroll
        for (int q = 0; q < 4; q++)
#pragma unroll
            for (int p = 0; p < 4; p++) acc[q][p] = bias2[q];

        __syncthreads();   // y tile + h(t-1) visible

#pragma unroll 4
        for (int k = 0; k < 192; k++) {
            float4 wv = *(const float4*)(wp0 + k * Gdim);
            unsigned long long w2[4];
            w2[0] = pack2(wv.x, wv.x); w2[1] = pack2(wv.y, wv.y);
            w2[2] = pack2(wv.z, wv.z); w2[3] = pack2(wv.w, wv.w);
            ulonglong2 hA = *(const ulonglong2*)(hp0 + k * HSTRIDE);
            ulonglong2 hB = *(const ulonglong2*)(hp0 + k * HSTRIDE + 4);
#pragma unroll
            for (int q = 0; q < 4; q++) {
                acc[q][0] = fma2(w2[q], hA.x, acc[q][0]);
                acc[q][1] = fma2(w2[q], hA.y, acc[q][1]);
                acc[q][2] = fma2(w2[q], hB.x, acc[q][2]);
                acc[q][3] = fma2(w2[q], hB.y, acc[q][3]);
            }
        }
        __syncthreads();   // reads done

        float hv[8];
#pragma unroll
        for (int p = 0; p < 4; p++) {
            float i0, i1, f0, f1, g0, g1, o0, o1;
            unpack2(acc[0][p], i0, i1); unpack2(acc[1][p], f0, f1);
            unpack2(acc[2][p], g0, g1); unpack2(acc[3][p], o0, o1);
            float cn0 = sigf(f0) * cst[2 * p]     + sigf(i0) * tanha(g0);
            float cn1 = sigf(f1) * cst[2 * p + 1] + sigf(i1) * tanha(g1);
            cst[2 * p] = cn0; cst[2 * p + 1] = cn1;
            hv[2 * p]     = sigf(o0) * tanha(cn0);
            hv[2 * p + 1] = sigf(o1) * tanha(cn1);
        }
        *(float4*)(sYT + (128 + c) * HSTRIDE + 8 * bo)     = make_float4(hv[0], hv[1], hv[2], hv[3]);
        *(float4*)(sYT + (128 + c) * HSTRIDE + 8 * bo + 4) = make_float4(hv[4], hv[5], hv[6], hv[7]);

        if (t == Lseq - 1) {
#pragma unroll
            for (int j = 0; j < 8; j++)
                g_hfin[(b0i + 8 * bo + j) * 128 + dir * 64 + c] = hv[j];
        }
    }
}

// ---------------- kernel 4: MLP head (smem-resident weights) ----------------
// grid 64, block 256. Block handles 32 batches; 8 threads per batch, 8 z-outputs each.
__global__ void __launch_bounds__(256)
head_kernel(const float* __restrict__ W1, const float* __restrict__ bf1,
            const float* __restrict__ W2, const float* __restrict__ bf2,
            float* __restrict__ out) {
    extern __shared__ float hs[];
    float* sW1 = hs;                 // [64][129]
    float* sh  = hs + 64 * 129;      // [32][129]
    float* sW2 = hs + 64 * 129 + 32 * 129;   // [64]
    float* sb1 = sW2 + 64;                   // [64]

    const int tid = threadIdx.x;
    const int b0 = blockIdx.x * 32;

    for (int i = tid; i < 64 * 128; i += 256) sW1[(i >> 7) * 129 + (i & 127)] = W1[i];
    for (int i = tid; i < 32 * 128; i += 256) sh[(i >> 7) * 129 + (i & 127)] = g_hfin[b0 * 128 + i];
    if (tid < 64) { sW2[tid] = W2[tid]; sb1[tid] = bf1[tid]; }
    __syncthreads();

    const int bi = tid >> 3, g8 = tid & 7;
    const float* hrow = sh + bi * 129;
    float part = 0.f;
#pragma unroll
    for (int jj = 0; jj < 8; jj++) {
        int j = g8 * 8 + jj;
        float z = sb1[j];
        const float* wrow = sW1 + j * 129;
#pragma unroll 16
        for (int k = 0; k < 128; k++) z += hrow[k] * wrow[k];
        part += fmaxf(z, 0.f) * sW2[j];
    }
#pragma unroll
    for (int o = 4; o; o >>= 1) part += __shfl_down_sync(0xffffffffu, part, o, 8);
    if (g8 == 0) out[b0 + bi] = part + bf2[0];
}

// ---------------- launch ----------------
extern "C" void kernel_launch(void* const* d_in, const int* in_sizes, int n_in,
                              void* d_out, int out_size) {
    const int*   x    = (const int*)  d_in[0];
    const float* emb  = (const float*)d_in[1];
    const float* Wih0 = (const float*)d_in[2];
    const float* Whh0 = (const float*)d_in[3];
    const float* b0   = (const float*)d_in[4];
    const float* Wih1 = (const float*)d_in[5];
    const float* Whh1 = (const float*)d_in[6];
    const float* b1   = (const float*)d_in[7];
    const float* W1   = (const float*)d_in[8];
    const float* bf1  = (const float*)d_in[9];
    const float* W2   = (const float*)d_in[10];
    const float* bf2  = (const float*)d_in[11];
    float* out = (float*)d_out;

    const int SMEM0 = (Hdim * Gdim + Hdim * HSTRIDE) * 4;         // 74752
    const int SMEM1 = (192 * Gdim + 192 * HSTRIDE) * 4;           // 224256
    const int SMEMH = (64 * 129 + 32 * 129 + 128) * 4;            // 50048
    static bool attr_done = false;
    if (!attr_done) {
        cudaFuncSetAttribute(lstm0_kernel, cudaFuncAttributeMaxDynamicSharedMemorySize, SMEM0);
        cudaFuncSetAttribute(lstm1_kernel, cudaFuncAttributeMaxDynamicSharedMemorySize, SMEM1);
        cudaFuncSetAttribute(head_kernel,  cudaFuncAttributeMaxDynamicSharedMemorySize, SMEMH);
        attr_done = true;
    }

    table_kernel<<<dim3(VOC, 2), Gdim>>>(emb, Wih0, b0);
    lstm0_kernel<<<dim3(Bsz / BT, 2), 256, SMEM0>>>(x, Whh0);
    lstm1_kernel<<<dim3(Bsz / BT, 2), 256, SMEM1>>>(Wih1, Whh1, b1);
    head_kernel<<<64, 256, SMEMH>>>(W1, bf1, W2, bf2, out);
}

// round 6
// speedup vs baseline: 2.8736x; 1.9028x over previous
#include <cuda_runtime.h>
#include <cuda_bf16.h>
#include <cstdint>

#define Bsz   2048
#define Lseq  256
#define NB    32

// ---------------- device scratch ----------------
__device__ __nv_bfloat16 g_y0hi[(size_t)Lseq * Bsz * 128];  // layer-0 output hi [t][b][128]
__device__ __nv_bfloat16 g_y0lo[(size_t)Lseq * Bsz * 128];  // layer-0 output lo
__device__ float g_hfin[Bsz * 128];                         // layer-1 final hidden [b][hf|hb]

// ---------------- helpers ----------------
__device__ __forceinline__ uint32_t s2u(const void* p) {
    uint32_t a;
    asm("{ .reg .u64 t; cvta.to.shared.u64 t, %1; cvt.u32.u64 %0, t; }" : "=r"(a) : "l"(p));
    return a;
}
__device__ __forceinline__ float tanha(float x) {
    float y; asm("tanh.approx.f32 %0, %1;" : "=f"(y) : "f"(x)); return y;
}
__device__ __forceinline__ float sigf(float x) { return fmaf(0.5f, tanha(0.5f * x), 0.5f); }

__device__ __forceinline__ void ldsm4(uint32_t* r, uint32_t addr) {
    asm volatile("ldmatrix.sync.aligned.m8n8.x4.shared.b16 {%0,%1,%2,%3}, [%4];"
        : "=r"(r[0]), "=r"(r[1]), "=r"(r[2]), "=r"(r[3]) : "r"(addr));
}
__device__ __forceinline__ void mmabf(float* d, const uint32_t* a, const uint32_t* b) {
    asm volatile("mma.sync.aligned.m16n8k16.row.col.f32.bf16.bf16.f32 "
        "{%0,%1,%2,%3}, {%4,%5,%6,%7}, {%8,%9}, {%0,%1,%2,%3};"
        : "+f"(d[0]), "+f"(d[1]), "+f"(d[2]), "+f"(d[3])
        : "r"(a[0]), "r"(a[1]), "r"(a[2]), "r"(a[3]), "r"(b[0]), "r"(b[1]));
}
// split fp32 -> (hi, lo) bf16 pair
__device__ __forceinline__ void split2(float v, __nv_bfloat16& hi, __nv_bfloat16& lo) {
    hi = __float2bfloat16(v);
    lo = __float2bfloat16(v - __bfloat162float(hi));
}

// ================= unified LSTM kernel =================
// FIRST: stage x from emb[token] (XC=64), write y->g_y0hi/lo.  else: stage y0 (XC=128), write g_hfin.
// A rows permuted: m = 32w+sub; cell = 8w+(sub&7); gate=(sub>>3)&3.
// Thread (w,lane): cell = 8w + (lane>>2); batches 8*nt + 2*(lane&3) + {0,1}.
// D = Whi*Bhi + Whi*Blo + Wlo*Bhi  (fp32-grade; lo*lo dropped)
template<int KT, bool FIRST>
__global__ void __launch_bounds__(256, 1)
lstm_kernel(const int* __restrict__ xtok, const float* __restrict__ embw,
            const float* __restrict__ Wih, const float* __restrict__ Whh,
            const float* __restrict__ bias) {
    constexpr int K  = KT * 16;
    constexpr int XC = K - 64;            // x-cols; h occupies XC..K-1
    constexpr int SA = K * 2 + 16;        // padded row stride (bytes)
    constexpr int PASSB = 256 * SA;       // one weight pass (hi or lo)
    constexpr int BOFF  = 2 * PASSB;      // B_hi region [32][K]
    constexpr int BSZB  = 32 * SA;
    constexpr int BLOFF = BOFF + BSZB;    // B_lo region

    extern __shared__ __align__(16) char smem[];
    const uint32_t sb = s2u(smem);

    const int dir = blockIdx.y;
    const int b0i = blockIdx.x * NB;
    const int tid = threadIdx.x, lane = tid & 31, w = tid >> 5;

    // ---- fill split weights (hi pass0, lo pass1), permuted rows ----
    {
        const int m = tid;
        const int cellm = 8 * (m >> 5) + (m & 7), gate = (m >> 3) & 3;
        const int grow = dir * 256 + gate * 64 + cellm;
        const float* si = Wih + (size_t)grow * XC;
        const float* sh = Whh + (size_t)grow * 64;
        char* rowp = smem + m * SA;
        for (int k = 0; k < K; k++) {
            float v = (k < XC) ? si[k] : sh[k - XC];
            __nv_bfloat16 hi, lo; split2(v, hi, lo);
            *(__nv_bfloat16*)(rowp + k * 2) = hi;
            *(__nv_bfloat16*)(rowp + PASSB + k * 2) = lo;
        }
    }
    // zero h regions of B_hi and B_lo (h0 = 0)
    {
        int row = tid >> 3, ch = tid & 7;
        *(uint4*)(smem + BOFF  + row * SA + (XC + ch * 8) * 2) = make_uint4(0, 0, 0, 0);
        *(uint4*)(smem + BLOFF + row * SA + (XC + ch * 8) * 2) = make_uint4(0, 0, 0, 0);
    }
    __syncthreads();

    // ---- ldmatrix lane addressing ----
    const int lrow = ((lane >> 3) & 1) * 8 + (lane & 7);
    const int lk8  = lane >> 4;
    const uint32_t a_base   = sb + (32 * w + lrow) * SA + lk8 * 16;
    const uint32_t alo_base = a_base + PASSB;
    const int bn  = 8 * (lane >> 4) + (lane & 7);
    const int bk8 = (lane >> 3) & 1;
    const uint32_t bh_base = sb + BOFF  + bn * SA + bk8 * 16;
    const uint32_t bl_base = sb + BLOFF + bn * SA + bk8 * 16;

    // ---- preload A-hi fragments (persist across all steps) ----
    uint32_t ahi0[KT][4], ahi1[KT][4];
#pragma unroll
    for (int kt = 0; kt < KT; kt++) {
        ldsm4(ahi0[kt], a_base + kt * 32);
        ldsm4(ahi1[kt], a_base + 16 * SA + kt * 32);
    }

    // ---- per-thread cell biases ----
    const int cell = 8 * w + (lane >> 2);
    const float* bp = bias + dir * 512;
    const float bi_ = bp[cell]       + bp[256 + cell];
    const float bf_ = bp[64 + cell]  + bp[320 + cell];
    const float bg_ = bp[128 + cell] + bp[384 + cell];
    const float bo_ = bp[192 + cell] + bp[448 + cell];

    float cs[4][2];
#pragma unroll
    for (int nt = 0; nt < 4; nt++) { cs[nt][0] = 0.f; cs[nt][1] = 0.f; }

    const int srow = tid >> 3, sch = tid & 7;   // staging / y-store indices

    for (int t = 0; t < Lseq; t++) {
        const int tcur = dir ? (Lseq - 1 - t) : t;

        // ---- stage x(t) into B_hi/B_lo cols 0..XC-1 ----
        if (FIRST) {
            int tok = __ldg(&xtok[(b0i + srow) * Lseq + tcur]);
            const float4* e = (const float4*)(embw + tok * 64 + sch * 8);
            float4 v0 = e[0], v1 = e[1];
            float vv[8] = {v0.x, v0.y, v0.z, v0.w, v1.x, v1.y, v1.z, v1.w};
            __nv_bfloat16 hi[8], lo[8];
#pragma unroll
            for (int j = 0; j < 8; j++) split2(vv[j], hi[j], lo[j]);
            *(uint4*)(smem + BOFF  + srow * SA + sch * 16) = *(uint4*)hi;
            *(uint4*)(smem + BLOFF + srow * SA + sch * 16) = *(uint4*)lo;
        } else {
#pragma unroll
            for (int s = 0; s < 2; s++) {
                int cid = tid + 256 * s, row = cid >> 4, ch = cid & 15;
                size_t gidx = ((size_t)tcur * Bsz + b0i + row) * 128 + ch * 8;
                *(uint4*)(smem + BOFF  + row * SA + ch * 16) = *(const uint4*)(g_y0hi + gidx);
                *(uint4*)(smem + BLOFF + row * SA + ch * 16) = *(const uint4*)(g_y0lo + gidx);
            }
        }
        __syncthreads();   // x(t) staged + h(t-1) visible

        // ---- y-store of h(t-1) (layer 0 only) ----
        if (FIRST && t > 0) {
            int tprev = dir ? (Lseq - t) : (t - 1);
            size_t gidx = ((size_t)tprev * Bsz + b0i + srow) * 128 + dir * 64 + sch * 8;
            *(uint4*)(g_y0hi + gidx) = *(uint4*)(smem + BOFF  + srow * SA + (64 + sch * 8) * 2);
            *(uint4*)(g_y0lo + gidx) = *(uint4*)(smem + BLOFF + srow * SA + (64 + sch * 8) * 2);
        }

        // ---- D = Whi*Bhi + Whi*Blo + Wlo*Bhi ----
        float acc[2][4][4];
#pragma unroll
        for (int mt = 0; mt < 2; mt++)
#pragma unroll
            for (int nt = 0; nt < 4; nt++)
#pragma unroll
                for (int r = 0; r < 4; r++) acc[mt][nt][r] = 0.f;

#pragma unroll
        for (int kt = 0; kt < KT; kt++) {
            uint32_t alo0[4], alo1[4], bh0[4], bh1[4], bl0[4], bl1[4];
            ldsm4(alo0, alo_base + kt * 32);
            ldsm4(alo1, alo_base + 16 * SA + kt * 32);
            ldsm4(bh0, bh_base + kt * 32);
            ldsm4(bh1, bh_base + 16 * SA + kt * 32);
            ldsm4(bl0, bl_base + kt * 32);
            ldsm4(bl1, bl_base + 16 * SA + kt * 32);

            mmabf(acc[0][0], ahi0[kt], bh0);     mmabf(acc[0][0], ahi0[kt], bl0);     mmabf(acc[0][0], alo0, bh0);
            mmabf(acc[0][1], ahi0[kt], bh0 + 2); mmabf(acc[0][1], ahi0[kt], bl0 + 2); mmabf(acc[0][1], alo0, bh0 + 2);
            mmabf(acc[0][2], ahi0[kt], bh1);     mmabf(acc[0][2], ahi0[kt], bl1);     mmabf(acc[0][2], alo0, bh1);
            mmabf(acc[0][3], ahi0[kt], bh1 + 2); mmabf(acc[0][3], ahi0[kt], bl1 + 2); mmabf(acc[0][3], alo0, bh1 + 2);
            mmabf(acc[1][0], ahi1[kt], bh0);     mmabf(acc[1][0], ahi1[kt], bl0);     mmabf(acc[1][0], alo1, bh0);
            mmabf(acc[1][1], ahi1[kt], bh0 + 2); mmabf(acc[1][1], ahi1[kt], bl0 + 2); mmabf(acc[1][1], alo1, bh0 + 2);
            mmabf(acc[1][2], ahi1[kt], bh1);     mmabf(acc[1][2], ahi1[kt], bl1);     mmabf(acc[1][2], alo1, bh1);
            mmabf(acc[1][3], ahi1[kt], bh1 + 2); mmabf(acc[1][3], ahi1[kt], bl1 + 2); mmabf(acc[1][3], alo1, bh1 + 2);
        }
        __syncthreads();   // all B reads complete before h(t) overwrite

        // ---- epilogue: i,f,g,o of one cell x 8 batches per thread ----
#pragma unroll
        for (int nt = 0; nt < 4; nt++) {
#pragma unroll
            for (int hh = 0; hh < 2; hh++) {
                int bb = 8 * nt + 2 * (lane & 3) + hh;
                float iv = acc[0][nt][hh]     + bi_;
                float fv = acc[0][nt][2 + hh] + bf_;
                float gv = acc[1][nt][hh]     + bg_;
                float ov = acc[1][nt][2 + hh] + bo_;
                float c = sigf(fv) * cs[nt][hh] + sigf(iv) * tanha(gv);
                cs[nt][hh] = c;
                float h = sigf(ov) * tanha(c);
                __nv_bfloat16 hi, lo; split2(h, hi, lo);
                *(__nv_bfloat16*)(smem + BOFF  + bb * SA + (XC + cell) * 2) = hi;
                *(__nv_bfloat16*)(smem + BLOFF + bb * SA + (XC + cell) * 2) = lo;
                if (!FIRST && t == Lseq - 1)
                    g_hfin[(b0i + bb) * 128 + dir * 64 + cell] = h;
            }
        }
    }

    // tail: flush y(last step) for layer 0
    if (FIRST) {
        __syncthreads();
        int tprev = dir ? 0 : (Lseq - 1);
        size_t gidx = ((size_t)tprev * Bsz + b0i + srow) * 128 + dir * 64 + sch * 8;
        *(uint4*)(g_y0hi + gidx) = *(uint4*)(smem + BOFF  + srow * SA + (64 + sch * 8) * 2);
        *(uint4*)(g_y0lo + gidx) = *(uint4*)(smem + BLOFF + srow * SA + (64 + sch * 8) * 2);
    }
}

// ================= MLP head =================
__global__ void __launch_bounds__(256)
head_kernel(const float* __restrict__ W1, const float* __restrict__ bf1,
            const float* __restrict__ W2, const float* __restrict__ bf2,
            float* __restrict__ out) {
    extern __shared__ float hs[];
    float* sW1 = hs;                           // [64][129]
    float* sh  = hs + 64 * 129;                // [32][129]
    float* sW2 = hs + 64 * 129 + 32 * 129;     // [64]
    float* sb1 = sW2 + 64;                     // [64]
    const int tid = threadIdx.x;
    const int b0 = blockIdx.x * 32;

    for (int i = tid; i < 64 * 128; i += 256) sW1[(i >> 7) * 129 + (i & 127)] = W1[i];
    for (int i = tid; i < 32 * 128; i += 256) sh[(i >> 7) * 129 + (i & 127)] = g_hfin[b0 * 128 + i];
    if (tid < 64) { sW2[tid] = W2[tid]; sb1[tid] = bf1[tid]; }
    __syncthreads();

    const int bi = tid >> 3, g8 = tid & 7;
    const float* hrow = sh + bi * 129;
    float part = 0.f;
#pragma unroll
    for (int jj = 0; jj < 8; jj++) {
        int j = g8 * 8 + jj;
        float z = sb1[j];
        const float* wrow = sW1 + j * 129;
#pragma unroll 16
        for (int k = 0; k < 128; k++) z += hrow[k] * wrow[k];
        part += fmaxf(z, 0.f) * sW2[j];
    }
#pragma unroll
    for (int o = 4; o; o >>= 1) part += __shfl_down_sync(0xffffffffu, part, o, 8);
    if (g8 == 0) out[b0 + bi] = part + bf2[0];
}

// ================= launch =================
extern "C" void kernel_launch(void* const* d_in, const int* in_sizes, int n_in,
                              void* d_out, int out_size) {
    const int*   x    = (const int*)  d_in[0];
    const float* emb  = (const float*)d_in[1];
    const float* Wih0 = (const float*)d_in[2];
    const float* Whh0 = (const float*)d_in[3];
    const float* b0   = (const float*)d_in[4];
    const float* Wih1 = (const float*)d_in[5];
    const float* Whh1 = (const float*)d_in[6];
    const float* b1   = (const float*)d_in[7];
    const float* W1   = (const float*)d_in[8];
    const float* bf1  = (const float*)d_in[9];
    const float* W2   = (const float*)d_in[10];
    const float* bf2  = (const float*)d_in[11];
    float* out = (float*)d_out;

    // smem: 2 weight passes [256][SA] + 2 B regions [32][SA]
    const int SM0 = (2 * 256 + 2 * 32) * (128 * 2 + 16);   // KT=8:  SA=272 -> 156672
    const int SM1 = (2 * 256 + 2 * 32) * (192 * 2 + 16);   // KT=12: SA=400 -> 230400
    const int SMH = (64 * 129 + 32 * 129 + 128) * 4;
    cudaFuncSetAttribute(lstm_kernel<8, true>,   cudaFuncAttributeMaxDynamicSharedMemorySize, SM0);
    cudaFuncSetAttribute(lstm_kernel<12, false>, cudaFuncAttributeMaxDynamicSharedMemorySize, SM1);
    cudaFuncSetAttribute(head_kernel,            cudaFuncAttributeMaxDynamicSharedMemorySize, SMH);

    lstm_kernel<8, true><<<dim3(Bsz / NB, 2), 256, SM0>>>(x, emb, Wih0, Whh0, b0);
    lstm_kernel<12, false><<<dim3(Bsz / NB, 2), 256, SM1>>>(x, emb, Wih1, Whh1, b1);
    head_kernel<<<64, 256, SMH>>>(W1, bf1, W2, bf2, out);
}

// round 8
// speedup vs baseline: 3.1585x; 1.0991x over previous
#include <cuda_runtime.h>
#include <cuda_bf16.h>
#include <cstdint>

#define Bsz   2048
#define Lseq  256
#define NB    32

// ---------------- device scratch ----------------
__device__ float g_T0[2 * 128 * 256];                       // token table [dir][tok][cell][gate4] fp32
__device__ __nv_bfloat16 g_y0hi[(size_t)Lseq * Bsz * 128];  // layer-0 output hi [t][b][128]
__device__ __nv_bfloat16 g_y0lo[(size_t)Lseq * Bsz * 128];  // layer-0 output lo
__device__ float g_hfin[Bsz * 128];                         // layer-1 final hidden [b][hf|hb]

// ---------------- helpers ----------------
__device__ __forceinline__ uint32_t s2u(const void* p) {
    uint32_t a;
    asm("{ .reg .u64 t; cvta.to.shared.u64 t, %1; cvt.u32.u64 %0, t; }" : "=r"(a) : "l"(p));
    return a;
}
__device__ __forceinline__ float tanha(float x) {
    float y; asm("tanh.approx.f32 %0, %1;" : "=f"(y) : "f"(x)); return y;
}
__device__ __forceinline__ float sigf(float x) { return fmaf(0.5f, tanha(0.5f * x), 0.5f); }

__device__ __forceinline__ void ldsm4(uint32_t* r, uint32_t addr) {
    asm volatile("ldmatrix.sync.aligned.m8n8.x4.shared.b16 {%0,%1,%2,%3}, [%4];"
        : "=r"(r[0]), "=r"(r[1]), "=r"(r[2]), "=r"(r[3]) : "r"(addr));
}
__device__ __forceinline__ void mmabf(float* d, const uint32_t* a, const uint32_t* b) {
    asm volatile("mma.sync.aligned.m16n8k16.row.col.f32.bf16.bf16.f32 "
        "{%0,%1,%2,%3}, {%4,%5,%6,%7}, {%8,%9}, {%0,%1,%2,%3};"
        : "+f"(d[0]), "+f"(d[1]), "+f"(d[2]), "+f"(d[3])
        : "r"(a[0]), "r"(a[1]), "r"(a[2]), "r"(a[3]), "r"(b[0]), "r"(b[1]));
}
__device__ __forceinline__ void split2(float v, __nv_bfloat16& hi, __nv_bfloat16& lo) {
    hi = __float2bfloat16(v);
    lo = __float2bfloat16(v - __bfloat162float(hi));
}

// ================= kernel 1: layer-0 token table (fp32 exact) =================
// T0[dir][v][cell][gate] = emb[v] . Wih0[dir][gate*64+cell] + b_ih + b_hh
__global__ void table_kernel(const float* __restrict__ emb,
                             const float* __restrict__ Wih0,
                             const float* __restrict__ b0) {
    const int v = blockIdx.x, dir = blockIdx.y, tid = threadIdx.x;
    const int cell = tid >> 2, gate = tid & 3;
    __shared__ float se[64];
    if (tid < 64) se[tid] = emb[v * 64 + tid];
    __syncthreads();
    const int grow = dir * 256 + gate * 64 + cell;
    const float* wrow = Wih0 + (size_t)grow * 64;
    float s = b0[dir * 512 + gate * 64 + cell] + b0[dir * 512 + 256 + gate * 64 + cell];
#pragma unroll
    for (int k = 0; k < 64; k++) s += se[k] * wrow[k];
    g_T0[((size_t)(dir * 128 + v) * 64 + cell) * 4 + gate] = s;
}

// ================= kernel 2: layer-0 LSTM (K=64 h-only, 3-pass, A hi+lo in regs) =================
// A rows permuted: m=32w+sub; cell=8w+(sub&7); gate=(sub>>3)&3.
// Thread (w,lane): cell = 8w+(lane>>2); batches 8*nt+2*(lane&3)+{0,1}.
__global__ void __launch_bounds__(256, 1)
lstm0_kernel(const int* __restrict__ xtok, const float* __restrict__ Whh0) {
    constexpr int SA = 144;                    // 64*2 + 16
    constexpr int ALO = 256 * SA;              // 36864
    constexpr int BH  = 2 * 256 * SA;          // 73728
    constexpr int BL  = BH + 32 * SA;          // 78336
    extern __shared__ __align__(16) char smem[];
    const uint32_t sb = s2u(smem);
    const int dir = blockIdx.y, b0i = blockIdx.x * NB;
    const int tid = threadIdx.x, lane = tid & 31, w = tid >> 5;

    // fill split Whh (hi, lo), permuted rows
    {
        const int m = tid;
        const int cellm = 8 * (m >> 5) + (m & 7), gate = (m >> 3) & 3;
        const float* sh = Whh0 + (size_t)(dir * 256 + gate * 64 + cellm) * 64;
        char* rowp = smem + m * SA;
#pragma unroll 8
        for (int k = 0; k < 64; k++) {
            __nv_bfloat16 hi, lo; split2(sh[k], hi, lo);
            *(__nv_bfloat16*)(rowp + k * 2) = hi;
            *(__nv_bfloat16*)(rowp + ALO + k * 2) = lo;
        }
    }
    { // zero h regions
        int row = tid >> 3, ch = tid & 7;
        *(uint4*)(smem + BH + row * SA + ch * 16) = make_uint4(0, 0, 0, 0);
        *(uint4*)(smem + BL + row * SA + ch * 16) = make_uint4(0, 0, 0, 0);
    }
    __syncthreads();

    // A fragments -> registers (hi + lo), persist all steps
    const int lrow = ((lane >> 3) & 1) * 8 + (lane & 7);
    const int lk8 = lane >> 4;
    const uint32_t a_base = sb + (32 * w + lrow) * SA + lk8 * 16;
    uint32_t ahi0[4][4], ahi1[4][4], alo0[4][4], alo1[4][4];
#pragma unroll
    for (int kt = 0; kt < 4; kt++) {
        ldsm4(ahi0[kt], a_base + kt * 32);
        ldsm4(ahi1[kt], a_base + 16 * SA + kt * 32);
        ldsm4(alo0[kt], a_base + ALO + kt * 32);
        ldsm4(alo1[kt], a_base + ALO + 16 * SA + kt * 32);
    }
    const int bn = 8 * (lane >> 4) + (lane & 7), bk8 = (lane >> 3) & 1;
    const uint32_t bh_base = sb + BH + bn * SA + bk8 * 16;
    const uint32_t bl_base = sb + BL + bn * SA + bk8 * 16;

    const int cell = 8 * w + (lane >> 2);
    float cs[4][2];
#pragma unroll
    for (int nt = 0; nt < 4; nt++) { cs[nt][0] = 0.f; cs[nt][1] = 0.f; }
    const int srow = tid >> 3, sch = tid & 7;
    const float* T0 = g_T0 + (size_t)dir * 128 * 256;

    for (int t = 0; t < Lseq; t++) {
        const int tcur = dir ? (Lseq - 1 - t) : t;
        __syncthreads();   // h(t-1) in B visible

        // y-store h(t-1): hi + lo
        if (t > 0) {
            int tprev = dir ? (Lseq - t) : (t - 1);
            size_t gidx = ((size_t)tprev * Bsz + b0i + srow) * 128 + dir * 64 + sch * 8;
            *(uint4*)(g_y0hi + gidx) = *(uint4*)(smem + BH + srow * SA + sch * 16);
            *(uint4*)(g_y0lo + gidx) = *(uint4*)(smem + BL + srow * SA + sch * 16);
        }

        // token-table gather (exact fp32 x-proj + biases)
        float4 tv[4][2];
#pragma unroll
        for (int nt = 0; nt < 4; nt++)
#pragma unroll
            for (int hh = 0; hh < 2; hh++) {
                int bb = 8 * nt + 2 * (lane & 3) + hh;
                int tok = __ldg(&xtok[(b0i + bb) * Lseq + tcur]);
                tv[nt][hh] = *(const float4*)(T0 + ((size_t)tok * 64 + cell) * 4);
            }

        // D = Whi*Bhi + Whi*Blo + Wlo*Bhi  (h-part only)
        float acc[2][4][4];
#pragma unroll
        for (int mt = 0; mt < 2; mt++)
#pragma unroll
            for (int nt = 0; nt < 4; nt++)
#pragma unroll
                for (int r = 0; r < 4; r++) acc[mt][nt][r] = 0.f;
#pragma unroll
        for (int kt = 0; kt < 4; kt++) {
            uint32_t bh0[4], bh1[4], bl0[4], bl1[4];
            ldsm4(bh0, bh_base + kt * 32);
            ldsm4(bh1, bh_base + 16 * SA + kt * 32);
            ldsm4(bl0, bl_base + kt * 32);
            ldsm4(bl1, bl_base + 16 * SA + kt * 32);
            mmabf(acc[0][0], ahi0[kt], bh0);     mmabf(acc[0][0], ahi0[kt], bl0);     mmabf(acc[0][0], alo0[kt], bh0);
            mmabf(acc[0][1], ahi0[kt], bh0 + 2); mmabf(acc[0][1], ahi0[kt], bl0 + 2); mmabf(acc[0][1], alo0[kt], bh0 + 2);
            mmabf(acc[0][2], ahi0[kt], bh1);     mmabf(acc[0][2], ahi0[kt], bl1);     mmabf(acc[0][2], alo0[kt], bh1);
            mmabf(acc[0][3], ahi0[kt], bh1 + 2); mmabf(acc[0][3], ahi0[kt], bl1 + 2); mmabf(acc[0][3], alo0[kt], bh1 + 2);
            mmabf(acc[1][0], ahi1[kt], bh0);     mmabf(acc[1][0], ahi1[kt], bl0);     mmabf(acc[1][0], alo1[kt], bh0);
            mmabf(acc[1][1], ahi1[kt], bh0 + 2); mmabf(acc[1][1], ahi1[kt], bl0 + 2); mmabf(acc[1][1], alo1[kt], bh0 + 2);
            mmabf(acc[1][2], ahi1[kt], bh1);     mmabf(acc[1][2], ahi1[kt], bl1);     mmabf(acc[1][2], alo1[kt], bh1);
            mmabf(acc[1][3], ahi1[kt], bh1 + 2); mmabf(acc[1][3], ahi1[kt], bl1 + 2); mmabf(acc[1][3], alo1[kt], bh1 + 2);
        }
        __syncthreads();   // all B reads done before h(t) overwrite

        // epilogue
#pragma unroll
        for (int nt = 0; nt < 4; nt++)
#pragma unroll
            for (int hh = 0; hh < 2; hh++) {
                float iv = acc[0][nt][hh]     + tv[nt][hh].x;
                float fv = acc[0][nt][2 + hh] + tv[nt][hh].y;
                float gv = acc[1][nt][hh]     + tv[nt][hh].z;
                float ov = acc[1][nt][2 + hh] + tv[nt][hh].w;
                float c = sigf(fv) * cs[nt][hh] + sigf(iv) * tanha(gv);
                cs[nt][hh] = c;
                float h = sigf(ov) * tanha(c);
                int bb = 8 * nt + 2 * (lane & 3) + hh;
                __nv_bfloat16 hi, lo; split2(h, hi, lo);
                *(__nv_bfloat16*)(smem + BH + bb * SA + cell * 2) = hi;
                *(__nv_bfloat16*)(smem + BL + bb * SA + cell * 2) = lo;
            }
    }
    __syncthreads();
    { // flush last step (hi + lo)
        int tprev = dir ? 0 : (Lseq - 1);
        size_t gidx = ((size_t)tprev * Bsz + b0i + srow) * 128 + dir * 64 + sch * 8;
        *(uint4*)(g_y0hi + gidx) = *(uint4*)(smem + BH + srow * SA + sch * 16);
        *(uint4*)(g_y0lo + gidx) = *(uint4*)(smem + BL + srow * SA + sch * 16);
    }
}

// ================= kernel 3: layer-1 LSTM (K=192, full 3-pass; round-6 proven) =================
__global__ void __launch_bounds__(256, 1)
lstm1_kernel(const float* __restrict__ Wih1, const float* __restrict__ Whh1,
             const float* __restrict__ bias) {
    constexpr int K  = 192;
    constexpr int XC = 128;
    constexpr int SA = K * 2 + 16;        // 400
    constexpr int PASSB = 256 * SA;       // 102400
    constexpr int BOFF  = 2 * PASSB;      // B_hi [32][K]
    constexpr int BSZB  = 32 * SA;
    constexpr int BLOFF = BOFF + BSZB;    // B_lo
    constexpr int KT = 12;

    extern __shared__ __align__(16) char smem[];
    const uint32_t sb = s2u(smem);
    const int dir = blockIdx.y, b0i = blockIdx.x * NB;
    const int tid = threadIdx.x, lane = tid & 31, w = tid >> 5;

    // fill split weights (hi, lo), permuted rows
    {
        const int m = tid;
        const int cellm = 8 * (m >> 5) + (m & 7), gate = (m >> 3) & 3;
        const int grow = dir * 256 + gate * 64 + cellm;
        const float* si = Wih1 + (size_t)grow * XC;
        const float* sh = Whh1 + (size_t)grow * 64;
        char* rowp = smem + m * SA;
        for (int k = 0; k < K; k++) {
            float v = (k < XC) ? si[k] : sh[k - XC];
            __nv_bfloat16 hi, lo; split2(v, hi, lo);
            *(__nv_bfloat16*)(rowp + k * 2) = hi;
            *(__nv_bfloat16*)(rowp + PASSB + k * 2) = lo;
        }
    }
    { // zero h regions of B_hi and B_lo
        int row = tid >> 3, ch = tid & 7;
        *(uint4*)(smem + BOFF  + row * SA + (XC + ch * 8) * 2) = make_uint4(0, 0, 0, 0);
        *(uint4*)(smem + BLOFF + row * SA + (XC + ch * 8) * 2) = make_uint4(0, 0, 0, 0);
    }
    __syncthreads();

    const int lrow = ((lane >> 3) & 1) * 8 + (lane & 7);
    const int lk8  = lane >> 4;
    const uint32_t a_base   = sb + (32 * w + lrow) * SA + lk8 * 16;
    const uint32_t alo_base = a_base + PASSB;
    const int bn  = 8 * (lane >> 4) + (lane & 7);
    const int bk8 = (lane >> 3) & 1;
    const uint32_t bh_base = sb + BOFF  + bn * SA + bk8 * 16;
    const uint32_t bl_base = sb + BLOFF + bn * SA + bk8 * 16;

    uint32_t ahi0[KT][4], ahi1[KT][4];
#pragma unroll
    for (int kt = 0; kt < KT; kt++) {
        ldsm4(ahi0[kt], a_base + kt * 32);
        ldsm4(ahi1[kt], a_base + 16 * SA + kt * 32);
    }

    const int cell = 8 * w + (lane >> 2);
    const float* bp = bias + dir * 512;
    const float bi_ = bp[cell]       + bp[256 + cell];
    const float bf_ = bp[64 + cell]  + bp[320 + cell];
    const float bg_ = bp[128 + cell] + bp[384 + cell];
    const float bo_ = bp[192 + cell] + bp[448 + cell];

    float cs[4][2];
#pragma unroll
    for (int nt = 0; nt < 4; nt++) { cs[nt][0] = 0.f; cs[nt][1] = 0.f; }

    for (int t = 0; t < Lseq; t++) {
        const int tcur = dir ? (Lseq - 1 - t) : t;

        // stage y0 hi+lo tile
#pragma unroll
        for (int s = 0; s < 2; s++) {
            int cid = tid + 256 * s, row = cid >> 4, ch = cid & 15;
            size_t gidx = ((size_t)tcur * Bsz + b0i + row) * 128 + ch * 8;
            *(uint4*)(smem + BOFF  + row * SA + ch * 16) = *(const uint4*)(g_y0hi + gidx);
            *(uint4*)(smem + BLOFF + row * SA + ch * 16) = *(const uint4*)(g_y0lo + gidx);
        }
        __syncthreads();   // x staged + h(t-1) visible

        float acc[2][4][4];
#pragma unroll
        for (int mt = 0; mt < 2; mt++)
#pragma unroll
            for (int nt = 0; nt < 4; nt++)
#pragma unroll
                for (int r = 0; r < 4; r++) acc[mt][nt][r] = 0.f;

#pragma unroll
        for (int kt = 0; kt < KT; kt++) {
            uint32_t alo0[4], alo1[4], bh0[4], bh1[4], bl0[4], bl1[4];
            ldsm4(alo0, alo_base + kt * 32);
            ldsm4(alo1, alo_base + 16 * SA + kt * 32);
            ldsm4(bh0, bh_base + kt * 32);
            ldsm4(bh1, bh_base + 16 * SA + kt * 32);
            ldsm4(bl0, bl_base + kt * 32);
            ldsm4(bl1, bl_base + 16 * SA + kt * 32);

            mmabf(acc[0][0], ahi0[kt], bh0);     mmabf(acc[0][0], ahi0[kt], bl0);     mmabf(acc[0][0], alo0, bh0);
            mmabf(acc[0][1], ahi0[kt], bh0 + 2); mmabf(acc[0][1], ahi0[kt], bl0 + 2); mmabf(acc[0][1], alo0, bh0 + 2);
            mmabf(acc[0][2], ahi0[kt], bh1);     mmabf(acc[0][2], ahi0[kt], bl1);     mmabf(acc[0][2], alo0, bh1);
            mmabf(acc[0][3], ahi0[kt], bh1 + 2); mmabf(acc[0][3], ahi0[kt], bl1 + 2); mmabf(acc[0][3], alo0, bh1 + 2);
            mmabf(acc[1][0], ahi1[kt], bh0);     mmabf(acc[1][0], ahi1[kt], bl0);     mmabf(acc[1][0], alo1, bh0);
            mmabf(acc[1][1], ahi1[kt], bh0 + 2); mmabf(acc[1][1], ahi1[kt], bl0 + 2); mmabf(acc[1][1], alo1, bh0 + 2);
            mmabf(acc[1][2], ahi1[kt], bh1);     mmabf(acc[1][2], ahi1[kt], bl1);     mmabf(acc[1][2], alo1, bh1);
            mmabf(acc[1][3], ahi1[kt], bh1 + 2); mmabf(acc[1][3], ahi1[kt], bl1 + 2); mmabf(acc[1][3], alo1, bh1 + 2);
        }
        __syncthreads();   // all B reads complete before h(t) overwrite

        // epilogue
#pragma unroll
        for (int nt = 0; nt < 4; nt++)
#pragma unroll
            for (int hh = 0; hh < 2; hh++) {
                int bb = 8 * nt + 2 * (lane & 3) + hh;
                float iv = acc[0][nt][hh]     + bi_;
                float fv = acc[0][nt][2 + hh] + bf_;
                float gv = acc[1][nt][hh]     + bg_;
                float ov = acc[1][nt][2 + hh] + bo_;
                float c = sigf(fv) * cs[nt][hh] + sigf(iv) * tanha(gv);
                cs[nt][hh] = c;
                float h = sigf(ov) * tanha(c);
                __nv_bfloat16 hi, lo; split2(h, hi, lo);
                *(__nv_bfloat16*)(smem + BOFF  + bb * SA + (XC + cell) * 2) = hi;
                *(__nv_bfloat16*)(smem + BLOFF + bb * SA + (XC + cell) * 2) = lo;
                if (t == Lseq - 1)
                    g_hfin[(b0i + bb) * 128 + dir * 64 + cell] = h;
            }
    }
}

// ================= kernel 4: MLP head =================
__global__ void __launch_bounds__(256)
head_kernel(const float* __restrict__ W1, const float* __restrict__ bf1,
            const float* __restrict__ W2, const float* __restrict__ bf2,
            float* __restrict__ out) {
    extern __shared__ float hs[];
    float* sW1 = hs;                           // [64][129]
    float* sh  = hs + 64 * 129;                // [32][129]
    float* sW2 = hs + 64 * 129 + 32 * 129;     // [64]
    float* sb1 = sW2 + 64;                     // [64]
    const int tid = threadIdx.x;
    const int b0 = blockIdx.x * 32;

    for (int i = tid; i < 64 * 128; i += 256) sW1[(i >> 7) * 129 + (i & 127)] = W1[i];
    for (int i = tid; i < 32 * 128; i += 256) sh[(i >> 7) * 129 + (i & 127)] = g_hfin[b0 * 128 + i];
    if (tid < 64) { sW2[tid] = W2[tid]; sb1[tid] = bf1[tid]; }
    __syncthreads();

    const int bi = tid >> 3, g8 = tid & 7;
    const float* hrow = sh + bi * 129;
    float part = 0.f;
#pragma unroll
    for (int jj = 0; jj < 8; jj++) {
        int j = g8 * 8 + jj;
        float z = sb1[j];
        const float* wrow = sW1 + j * 129;
#pragma unroll 16
        for (int k = 0; k < 128; k++) z += hrow[k] * wrow[k];
        part += fmaxf(z, 0.f) * sW2[j];
    }
#pragma unroll
    for (int o = 4; o; o >>= 1) part += __shfl_down_sync(0xffffffffu, part, o, 8);
    if (g8 == 0) out[b0 + bi] = part + bf2[0];
}

// ================= launch =================
extern "C" void kernel_launch(void* const* d_in, const int* in_sizes, int n_in,
                              void* d_out, int out_size) {
    const int*   x    = (const int*)  d_in[0];
    const float* emb  = (const float*)d_in[1];
    const float* Wih0 = (const float*)d_in[2];
    const float* Whh0 = (const float*)d_in[3];
    const float* b0   = (const float*)d_in[4];
    const float* Wih1 = (const float*)d_in[5];
    const float* Whh1 = (const float*)d_in[6];
    const float* b1   = (const float*)d_in[7];
    const float* W1   = (const float*)d_in[8];
    const float* bf1  = (const float*)d_in[9];
    const float* W2   = (const float*)d_in[10];
    const float* bf2  = (const float*)d_in[11];
    float* out = (float*)d_out;

    const int SM0 = 2 * 256 * 144 + 2 * 32 * 144;          // 82944
    const int SM1 = (2 * 256 + 2 * 32) * 400;              // 230400
    const int SMH = (64 * 129 + 32 * 129 + 128) * 4;
    cudaFuncSetAttribute(lstm0_kernel, cudaFuncAttributeMaxDynamicSharedMemorySize, SM0);
    cudaFuncSetAttribute(lstm1_kernel, cudaFuncAttributeMaxDynamicSharedMemorySize, SM1);
    cudaFuncSetAttribute(head_kernel,  cudaFuncAttributeMaxDynamicSharedMemorySize, SMH);

    table_kernel<<<dim3(128, 2), 256>>>(emb, Wih0, b0);
    lstm0_kernel<<<dim3(Bsz / NB, 2), 256, SM0>>>(x, Whh0);
    lstm1_kernel<<<dim3(Bsz / NB, 2), 256, SM1>>>(Wih1, Whh1, b1);
    head_kernel<<<64, 256, SMH>>>(W1, bf1, W2, bf2, out);
}

// round 9
// speedup vs baseline: 4.6218x; 1.4633x over previous
#include <cuda_runtime.h>
#include <cuda_fp16.h>
#include <cstdint>

#define Bsz   2048
#define Lseq  256
#define NB    32

// ---------------- device scratch ----------------
__device__ float g_T0[2 * 128 * 256];                 // token table [dir][tok][cell][gate4] fp32
__device__ __half g_y0[(size_t)Lseq * Bsz * 128];     // layer-0 output fp16 [t][b][128]
__device__ float g_hfin[Bsz * 128];                   // layer-1 final hidden [b][hf|hb]

// ---------------- helpers ----------------
__device__ __forceinline__ uint32_t s2u(const void* p) {
    uint32_t a;
    asm("{ .reg .u64 t; cvta.to.shared.u64 t, %1; cvt.u32.u64 %0, t; }" : "=r"(a) : "l"(p));
    return a;
}
__device__ __forceinline__ float tanha(float x) {
    float y; asm("tanh.approx.f32 %0, %1;" : "=f"(y) : "f"(x)); return y;
}
__device__ __forceinline__ float sigf(float x) { return fmaf(0.5f, tanha(0.5f * x), 0.5f); }

__device__ __forceinline__ void ldsm4(uint32_t* r, uint32_t addr) {
    asm volatile("ldmatrix.sync.aligned.m8n8.x4.shared.b16 {%0,%1,%2,%3}, [%4];"
        : "=r"(r[0]), "=r"(r[1]), "=r"(r[2]), "=r"(r[3]) : "r"(addr));
}
__device__ __forceinline__ void mmaf16(float* d, const uint32_t* a, const uint32_t* b) {
    asm volatile("mma.sync.aligned.m16n8k16.row.col.f32.f16.f16.f32 "
        "{%0,%1,%2,%3}, {%4,%5,%6,%7}, {%8,%9}, {%0,%1,%2,%3};"
        : "+f"(d[0]), "+f"(d[1]), "+f"(d[2]), "+f"(d[3])
        : "r"(a[0]), "r"(a[1]), "r"(a[2]), "r"(a[3]), "r"(b[0]), "r"(b[1]));
}
// split fp32 -> (hi, lo) fp16 pair (covers ~22 mantissa bits)
__device__ __forceinline__ void split2h(float v, __half& hi, __half& lo) {
    hi = __float2half_rn(v);
    lo = __float2half_rn(v - __half2float(hi));
}

// ================= kernel 1: layer-0 token table (fp32 exact) =================
// T0[dir][v][cell][gate] = emb[v] . Wih0[dir][gate*64+cell] + b_ih + b_hh
__global__ void table_kernel(const float* __restrict__ emb,
                             const float* __restrict__ Wih0,
                             const float* __restrict__ b0) {
    const int v = blockIdx.x, dir = blockIdx.y, tid = threadIdx.x;
    const int cell = tid >> 2, gate = tid & 3;
    __shared__ float se[64];
    if (tid < 64) se[tid] = emb[v * 64 + tid];
    __syncthreads();
    const float* wrow = Wih0 + (size_t)(dir * 256 + gate * 64 + cell) * 64;
    float s = b0[dir * 512 + gate * 64 + cell] + b0[dir * 512 + 256 + gate * 64 + cell];
#pragma unroll
    for (int k = 0; k < 64; k++) s += se[k] * wrow[k];
    g_T0[((size_t)(dir * 128 + v) * 64 + cell) * 4 + gate] = s;
}

// ================= kernel 2: layer-0 LSTM (K=64 h-only, fp16 2-pass, A hi+lo in regs) =================
// A rows permuted: m=32w+sub; cell=8w+(sub&7); gate=(sub>>3)&3.
// Thread (w,lane): cell = 8w+(lane>>2); batches 8*nt+2*(lane&3)+{0,1}.
// D = Whi*B + Wlo*B  (weights exact, h activation fp16)
__global__ void __launch_bounds__(256, 1)
lstm0_kernel(const int* __restrict__ xtok, const float* __restrict__ Whh0) {
    constexpr int SA  = 144;                   // 64*2 + 16
    constexpr int ALO = 256 * SA;              // 36864
    constexpr int BH  = 2 * 256 * SA;          // 73728
    extern __shared__ __align__(16) char smem[];
    const uint32_t sb = s2u(smem);
    const int dir = blockIdx.y, b0i = blockIdx.x * NB;
    const int tid = threadIdx.x, lane = tid & 31, w = tid >> 5;

    // fill split Whh (hi, lo), permuted rows
    {
        const int m = tid;
        const int cellm = 8 * (m >> 5) + (m & 7), gate = (m >> 3) & 3;
        const float* sh = Whh0 + (size_t)(dir * 256 + gate * 64 + cellm) * 64;
        char* rowp = smem + m * SA;
#pragma unroll 8
        for (int k = 0; k < 64; k++) {
            __half hi, lo; split2h(sh[k], hi, lo);
            *(__half*)(rowp + k * 2) = hi;
            *(__half*)(rowp + ALO + k * 2) = lo;
        }
    }
    { // zero h region
        int row = tid >> 3, ch = tid & 7;
        *(uint4*)(smem + BH + row * SA + ch * 16) = make_uint4(0, 0, 0, 0);
    }
    __syncthreads();

    // A fragments -> registers (hi + lo), persist all steps
    const int lrow = ((lane >> 3) & 1) * 8 + (lane & 7);
    const int lk8 = lane >> 4;
    const uint32_t a_base = sb + (32 * w + lrow) * SA + lk8 * 16;
    uint32_t ahi0[4][4], ahi1[4][4], alo0[4][4], alo1[4][4];
#pragma unroll
    for (int kt = 0; kt < 4; kt++) {
        ldsm4(ahi0[kt], a_base + kt * 32);
        ldsm4(ahi1[kt], a_base + 16 * SA + kt * 32);
        ldsm4(alo0[kt], a_base + ALO + kt * 32);
        ldsm4(alo1[kt], a_base + ALO + 16 * SA + kt * 32);
    }
    const int bn = 8 * (lane >> 4) + (lane & 7), bk8 = (lane >> 3) & 1;
    const uint32_t bh_base = sb + BH + bn * SA + bk8 * 16;

    const int cell = 8 * w + (lane >> 2);
    float cs[4][2];
#pragma unroll
    for (int nt = 0; nt < 4; nt++) { cs[nt][0] = 0.f; cs[nt][1] = 0.f; }
    const int srow = tid >> 3, sch = tid & 7;
    const float* T0 = g_T0 + (size_t)dir * 128 * 256;

    for (int t = 0; t < Lseq; t++) {
        const int tcur = dir ? (Lseq - 1 - t) : t;
        __syncthreads();   // h(t-1) in B visible

        // y-store h(t-1)
        if (t > 0) {
            int tprev = dir ? (Lseq - t) : (t - 1);
            *(uint4*)(g_y0 + ((size_t)tprev * Bsz + b0i + srow) * 128 + dir * 64 + sch * 8)
                = *(uint4*)(smem + BH + srow * SA + sch * 16);
        }

        // token-table gather (exact fp32 x-proj + biases) — overlaps mma loop
        float4 tv[4][2];
#pragma unroll
        for (int nt = 0; nt < 4; nt++)
#pragma unroll
            for (int hh = 0; hh < 2; hh++) {
                int bb = 8 * nt + 2 * (lane & 3) + hh;
                int tok = __ldg(&xtok[(b0i + bb) * Lseq + tcur]);
                tv[nt][hh] = *(const float4*)(T0 + ((size_t)tok * 64 + cell) * 4);
            }

        // D = Whi*B + Wlo*B
        float acc[2][4][4];
#pragma unroll
        for (int mt = 0; mt < 2; mt++)
#pragma unroll
            for (int nt = 0; nt < 4; nt++)
#pragma unroll
                for (int r = 0; r < 4; r++) acc[mt][nt][r] = 0.f;
#pragma unroll
        for (int kt = 0; kt < 4; kt++) {
            uint32_t bh0[4], bh1[4];
            ldsm4(bh0, bh_base + kt * 32);
            ldsm4(bh1, bh_base + 16 * SA + kt * 32);
            mmaf16(acc[0][0], ahi0[kt], bh0);     mmaf16(acc[0][0], alo0[kt], bh0);
            mmaf16(acc[0][1], ahi0[kt], bh0 + 2); mmaf16(acc[0][1], alo0[kt], bh0 + 2);
            mmaf16(acc[0][2], ahi0[kt], bh1);     mmaf16(acc[0][2], alo0[kt], bh1);
            mmaf16(acc[0][3], ahi0[kt], bh1 + 2); mmaf16(acc[0][3], alo0[kt], bh1 + 2);
            mmaf16(acc[1][0], ahi1[kt], bh0);     mmaf16(acc[1][0], alo1[kt], bh0);
            mmaf16(acc[1][1], ahi1[kt], bh0 + 2); mmaf16(acc[1][1], alo1[kt], bh0 + 2);
            mmaf16(acc[1][2], ahi1[kt], bh1);     mmaf16(acc[1][2], alo1[kt], bh1);
            mmaf16(acc[1][3], ahi1[kt], bh1 + 2); mmaf16(acc[1][3], alo1[kt], bh1 + 2);
        }
        __syncthreads();   // all B reads done before h(t) overwrite

        // epilogue
#pragma unroll
        for (int nt = 0; nt < 4; nt++)
#pragma unroll
            for (int hh = 0; hh < 2; hh++) {
                float iv = acc[0][nt][hh]     + tv[nt][hh].x;
                float fv = acc[0][nt][2 + hh] + tv[nt][hh].y;
                float gv = acc[1][nt][hh]     + tv[nt][hh].z;
                float ov = acc[1][nt][2 + hh] + tv[nt][hh].w;
                float c = sigf(fv) * cs[nt][hh] + sigf(iv) * tanha(gv);
                cs[nt][hh] = c;
                float h = sigf(ov) * tanha(c);
                int bb = 8 * nt + 2 * (lane & 3) + hh;
                *(__half*)(smem + BH + bb * SA + cell * 2) = __float2half_rn(h);
            }
    }
    __syncthreads();
    { // flush last step
        int tprev = dir ? 0 : (Lseq - 1);
        *(uint4*)(g_y0 + ((size_t)tprev * Bsz + b0i + srow) * 128 + dir * 64 + sch * 8)
            = *(uint4*)(smem + BH + srow * SA + sch * 16);
    }
}

// ================= kernel 3: layer-1 LSTM (K=192, fp16 2-pass, pipelined staging) =================
__global__ void __launch_bounds__(256, 1)
lstm1_kernel(const float* __restrict__ Wih1, const float* __restrict__ Whh1,
             const float* __restrict__ bias) {
    constexpr int K  = 192;
    constexpr int XC = 128;
    constexpr int SA = K * 2 + 16;        // 400
    constexpr int ALO = 256 * SA;         // 102400
    constexpr int BOFF = 2 * ALO;         // 204800, B [32][K] fp16
    constexpr int KT = 12;

    extern __shared__ __align__(16) char smem[];
    const uint32_t sb = s2u(smem);
    const int dir = blockIdx.y, b0i = blockIdx.x * NB;
    const int tid = threadIdx.x, lane = tid & 31, w = tid >> 5;

    // fill split weights (hi, lo), permuted rows
    {
        const int m = tid;
        const int cellm = 8 * (m >> 5) + (m & 7), gate = (m >> 3) & 3;
        const int grow = dir * 256 + gate * 64 + cellm;
        const float* si = Wih1 + (size_t)grow * XC;
        const float* sh = Whh1 + (size_t)grow * 64;
        char* rowp = smem + m * SA;
        for (int k = 0; k < K; k++) {
            float v = (k < XC) ? si[k] : sh[k - XC];
            __half hi, lo; split2h(v, hi, lo);
            *(__half*)(rowp + k * 2) = hi;
            *(__half*)(rowp + ALO + k * 2) = lo;
        }
    }
    { // zero h region of B
        int row = tid >> 3, ch = tid & 7;
        *(uint4*)(smem + BOFF + row * SA + (XC + ch * 8) * 2) = make_uint4(0, 0, 0, 0);
    }

    const int lrow = ((lane >> 3) & 1) * 8 + (lane & 7);
    const int lk8  = lane >> 4;
    const uint32_t a_base   = sb + (32 * w + lrow) * SA + lk8 * 16;
    const uint32_t alo_base = a_base + ALO;
    const int bn  = 8 * (lane >> 4) + (lane & 7);
    const int bk8 = (lane >> 3) & 1;
    const uint32_t bh_base = sb + BOFF + bn * SA + bk8 * 16;

    // staging indices: per thread 2 chunks of x tile
    const int r0 = tid >> 4, c0 = tid & 15;          // s=0: row r0, chunk c0
    const int r1 = (tid + 256) >> 4, c1 = tid & 15;  // s=1

    // prologue: stage x(t=0)
    {
        int tn = dir ? (Lseq - 1) : 0;
        *(uint4*)(smem + BOFF + r0 * SA + c0 * 16)
            = *(const uint4*)(g_y0 + ((size_t)tn * Bsz + b0i + r0) * 128 + c0 * 8);
        *(uint4*)(smem + BOFF + r1 * SA + c1 * 16)
            = *(const uint4*)(g_y0 + ((size_t)tn * Bsz + b0i + r1) * 128 + c1 * 8);
    }
    __syncthreads();

    // A-hi fragments -> registers
    uint32_t ahi0[KT][4], ahi1[KT][4];
#pragma unroll
    for (int kt = 0; kt < KT; kt++) {
        ldsm4(ahi0[kt], a_base + kt * 32);
        ldsm4(ahi1[kt], a_base + 16 * SA + kt * 32);
    }

    const int cell = 8 * w + (lane >> 2);
    const float* bp = bias + dir * 512;
    const float bi_ = bp[cell]       + bp[256 + cell];
    const float bf_ = bp[64 + cell]  + bp[320 + cell];
    const float bg_ = bp[128 + cell] + bp[384 + cell];
    const float bo_ = bp[192 + cell] + bp[448 + cell];

    float cs[4][2];
#pragma unroll
    for (int nt = 0; nt < 4; nt++) { cs[nt][0] = 0.f; cs[nt][1] = 0.f; }
    __syncthreads();   // x(0) staged (also covers A reg loads)

    for (int t = 0; t < Lseq; t++) {
        // prefetch x(t+1) into registers — overlaps mma loop
        uint4 pf0, pf1;
        if (t + 1 < Lseq) {
            int tn = dir ? (Lseq - 2 - t) : (t + 1);
            pf0 = *(const uint4*)(g_y0 + ((size_t)tn * Bsz + b0i + r0) * 128 + c0 * 8);
            pf1 = *(const uint4*)(g_y0 + ((size_t)tn * Bsz + b0i + r1) * 128 + c1 * 8);
        }

        // D = Whi*B + Wlo*B
        float acc[2][4][4];
#pragma unroll
        for (int mt = 0; mt < 2; mt++)
#pragma unroll
            for (int nt = 0; nt < 4; nt++)
#pragma unroll
                for (int r = 0; r < 4; r++) acc[mt][nt][r] = 0.f;

#pragma unroll
        for (int kt = 0; kt < KT; kt++) {
            uint32_t alo0[4], alo1[4], bh0[4], bh1[4];
            ldsm4(alo0, alo_base + kt * 32);
            ldsm4(alo1, alo_base + 16 * SA + kt * 32);
            ldsm4(bh0, bh_base + kt * 32);
            ldsm4(bh1, bh_base + 16 * SA + kt * 32);
            mmaf16(acc[0][0], ahi0[kt], bh0);     mmaf16(acc[0][0], alo0, bh0);
            mmaf16(acc[0][1], ahi0[kt], bh0 + 2); mmaf16(acc[0][1], alo0, bh0 + 2);
            mmaf16(acc[0][2], ahi0[kt], bh1);     mmaf16(acc[0][2], alo0, bh1);
            mmaf16(acc[0][3], ahi0[kt], bh1 + 2); mmaf16(acc[0][3], alo0, bh1 + 2);
            mmaf16(acc[1][0], ahi1[kt], bh0);     mmaf16(acc[1][0], alo1, bh0);
            mmaf16(acc[1][1], ahi1[kt], bh0 + 2); mmaf16(acc[1][1], alo1, bh0 + 2);
            mmaf16(acc[1][2], ahi1[kt], bh1);     mmaf16(acc[1][2], alo1, bh1);
            mmaf16(acc[1][3], ahi1[kt], bh1 + 2); mmaf16(acc[1][3], alo1, bh1 + 2);
        }
        __syncthreads();   // all B reads complete before overwrite

        // epilogue: h(t) -> B h-region
#pragma unroll
        for (int nt = 0; nt < 4; nt++)
#pragma unroll
            for (int hh = 0; hh < 2; hh++) {
                int bb = 8 * nt + 2 * (lane & 3) + hh;
                float iv = acc[0][nt][hh]     + bi_;
                float fv = acc[0][nt][2 + hh] + bf_;
                float gv = acc[1][nt][hh]     + bg_;
                float ov = acc[1][nt][2 + hh] + bo_;
                float c = sigf(fv) * cs[nt][hh] + sigf(iv) * tanha(gv);
                cs[nt][hh] = c;
                float h = sigf(ov) * tanha(c);
                *(__half*)(smem + BOFF + bb * SA + (XC + cell) * 2) = __float2half_rn(h);
                if (t == Lseq - 1)
                    g_hfin[(b0i + bb) * 128 + dir * 64 + cell] = h;
            }

        // store prefetched x(t+1)
        if (t + 1 < Lseq) {
            *(uint4*)(smem + BOFF + r0 * SA + c0 * 16) = pf0;
            *(uint4*)(smem + BOFF + r1 * SA + c1 * 16) = pf1;
        }
        __syncthreads();   // x(t+1) + h(t) visible for next iteration
    }
}

// ================= kernel 4: MLP head =================
__global__ void __launch_bounds__(256)
head_kernel(const float* __restrict__ W1, const float* __restrict__ bf1,
            const float* __restrict__ W2, const float* __restrict__ bf2,
            float* __restrict__ out) {
    extern __shared__ float hs[];
    float* sW1 = hs;                           // [64][129]
    float* sh  = hs + 64 * 129;                // [32][129]
    float* sW2 = hs + 64 * 129 + 32 * 129;     // [64]
    float* sb1 = sW2 + 64;                     // [64]
    const int tid = threadIdx.x;
    const int b0 = blockIdx.x * 32;

    for (int i = tid; i < 64 * 128; i += 256) sW1[(i >> 7) * 129 + (i & 127)] = W1[i];
    for (int i = tid; i < 32 * 128; i += 256) sh[(i >> 7) * 129 + (i & 127)] = g_hfin[b0 * 128 + i];
    if (tid < 64) { sW2[tid] = W2[tid]; sb1[tid] = bf1[tid]; }
    __syncthreads();

    const int bi = tid >> 3, g8 = tid & 7;
    const float* hrow = sh + bi * 129;
    float part = 0.f;
#pragma unroll
    for (int jj = 0; jj < 8; jj++) {
        int j = g8 * 8 + jj;
        float z = sb1[j];
        const float* wrow = sW1 + j * 129;
#pragma unroll 16
        for (int k = 0; k < 128; k++) z += hrow[k] * wrow[k];
        part += fmaxf(z, 0.f) * sW2[j];
    }
#pragma unroll
    for (int o = 4; o; o >>= 1) part += __shfl_down_sync(0xffffffffu, part, o, 8);
    if (g8 == 0) out[b0 + bi] = part + bf2[0];
}

// ================= launch =================
extern "C" void kernel_launch(void* const* d_in, const int* in_sizes, int n_in,
                              void* d_out, int out_size) {
    const int*   x    = (const int*)  d_in[0];
    const float* emb  = (const float*)d_in[1];
    const float* Wih0 = (const float*)d_in[2];
    const float* Whh0 = (const float*)d_in[3];
    const float* b0   = (const float*)d_in[4];
    const float* Wih1 = (const float*)d_in[5];
    const float* Whh1 = (const float*)d_in[6];
    const float* b1   = (const float*)d_in[7];
    const float* W1   = (const float*)d_in[8];
    const float* bf1  = (const float*)d_in[9];
    const float* W2   = (const float*)d_in[10];
    const float* bf2  = (const float*)d_in[11];
    float* out = (float*)d_out;

    const int SM0 = 2 * 256 * 144 + 32 * 144;              // 78336
    const int SM1 = 2 * 256 * 400 + 32 * 400;              // 217600
    const int SMH = (64 * 129 + 32 * 129 + 128) * 4;
    cudaFuncSetAttribute(lstm0_kernel, cudaFuncAttributeMaxDynamicSharedMemorySize, SM0);
    cudaFuncSetAttribute(lstm1_kernel, cudaFuncAttributeMaxDynamicSharedMemorySize, SM1);
    cudaFuncSetAttribute(head_kernel,  cudaFuncAttributeMaxDynamicSharedMemorySize, SMH);

    table_kernel<<<dim3(128, 2), 256>>>(emb, Wih0, b0);
    lstm0_kernel<<<dim3(Bsz / NB, 2), 256, SM0>>>(x, Whh0);
    lstm1_kernel<<<dim3(Bsz / NB, 2), 256, SM1>>>(Wih1, Whh1, b1);
    head_kernel<<<64, 256, SMH>>>(W1, bf1, W2, bf2, out);
}

// round 10
// speedup vs baseline: 5.5498x; 1.2008x over previous
#include <cuda_runtime.h>
#include <cuda_fp16.h>
#include <cstdint>

#define Bsz   2048
#define Lseq  256
#define NB    32

// ---------------- device scratch ----------------
__device__ float g_T0[2 * 128 * 256];                 // token table [dir][tok][cell][gate4] fp32
__device__ __half g_y0[(size_t)Lseq * Bsz * 128];     // layer-0 output fp16 [t][b][128]
__device__ float g_hfin[Bsz * 128];                   // layer-1 final hidden [b][hf|hb]

// ---------------- helpers ----------------
__device__ __forceinline__ uint32_t s2u(const void* p) {
    uint32_t a;
    asm("{ .reg .u64 t; cvta.to.shared.u64 t, %1; cvt.u32.u64 %0, t; }" : "=r"(a) : "l"(p));
    return a;
}
__device__ __forceinline__ float tanha(float x) {
    float y; asm("tanh.approx.f32 %0, %1;" : "=f"(y) : "f"(x)); return y;
}
__device__ __forceinline__ float sigf(float x) { return fmaf(0.5f, tanha(0.5f * x), 0.5f); }

__device__ __forceinline__ void ldsm4(uint32_t* r, uint32_t addr) {
    asm volatile("ldmatrix.sync.aligned.m8n8.x4.shared.b16 {%0,%1,%2,%3}, [%4];"
        : "=r"(r[0]), "=r"(r[1]), "=r"(r[2]), "=r"(r[3]) : "r"(addr));
}
__device__ __forceinline__ void mmaf16(float* d, const uint32_t* a, const uint32_t* b) {
    asm volatile("mma.sync.aligned.m16n8k16.row.col.f32.f16.f16.f32 "
        "{%0,%1,%2,%3}, {%4,%5,%6,%7}, {%8,%9}, {%0,%1,%2,%3};"
        : "+f"(d[0]), "+f"(d[1]), "+f"(d[2]), "+f"(d[3])
        : "r"(a[0]), "r"(a[1]), "r"(a[2]), "r"(a[3]), "r"(b[0]), "r"(b[1]));
}
__device__ __forceinline__ void split2h(float v, __half& hi, __half& lo) {
    hi = __float2half_rn(v);
    lo = __float2half_rn(v - __half2float(hi));
}

// ================= kernel 1: layer-0 token table (fp32 exact) =================
__global__ void table_kernel(const float* __restrict__ emb,
                             const float* __restrict__ Wih0,
                             const float* __restrict__ b0) {
    const int v = blockIdx.x, dir = blockIdx.y, tid = threadIdx.x;
    const int cell = tid >> 2, gate = tid & 3;
    __shared__ float se[64];
    if (tid < 64) se[tid] = emb[v * 64 + tid];
    __syncthreads();
    const float* wrow = Wih0 + (size_t)(dir * 256 + gate * 64 + cell) * 64;
    float s = b0[dir * 512 + gate * 64 + cell] + b0[dir * 512 + 256 + gate * 64 + cell];
#pragma unroll
    for (int k = 0; k < 64; k++) s += se[k] * wrow[k];
    g_T0[((size_t)(dir * 128 + v) * 64 + cell) * 4 + gate] = s;
}

// ================= kernel 2: layer-0 LSTM =================
// K=64 h-only (x via exact table), fp16 2-pass weights, A hi+lo in regs,
// double-buffered h, ONE barrier/step.
__global__ void __launch_bounds__(256, 1)
lstm0_kernel(const int* __restrict__ xtok, const float* __restrict__ Whh0) {
    constexpr int SA  = 144;                   // 64*2 + 16
    constexpr int ALO = 256 * SA;              // 36864
    constexpr int BH0 = 2 * 256 * SA;          // 73728
    constexpr int BH1 = BH0 + 32 * SA;         // 78336  (total 82944)
    extern __shared__ __align__(16) char smem[];
    const uint32_t sb = s2u(smem);
    const int dir = blockIdx.y, b0i = blockIdx.x * NB;
    const int tid = threadIdx.x, lane = tid & 31, w = tid >> 5;

    // fill split Whh (hi, lo), permuted rows
    {
        const int m = tid;
        const int cellm = 8 * (m >> 5) + (m & 7), gate = (m >> 3) & 3;
        const float* sh = Whh0 + (size_t)(dir * 256 + gate * 64 + cellm) * 64;
        char* rowp = smem + m * SA;
#pragma unroll 8
        for (int k = 0; k < 64; k++) {
            __half hi, lo; split2h(sh[k], hi, lo);
            *(__half*)(rowp + k * 2) = hi;
            *(__half*)(rowp + ALO + k * 2) = lo;
        }
    }
    { // zero h buffer 0 (h(-1) = 0)
        int row = tid >> 3, ch = tid & 7;
        *(uint4*)(smem + BH0 + row * SA + ch * 16) = make_uint4(0, 0, 0, 0);
    }
    __syncthreads();

    // A fragments -> registers (hi + lo)
    const int lrow = ((lane >> 3) & 1) * 8 + (lane & 7);
    const int lk8 = lane >> 4;
    const uint32_t a_base = sb + (32 * w + lrow) * SA + lk8 * 16;
    uint32_t ahi0[4][4], ahi1[4][4], alo0[4][4], alo1[4][4];
#pragma unroll
    for (int kt = 0; kt < 4; kt++) {
        ldsm4(ahi0[kt], a_base + kt * 32);
        ldsm4(ahi1[kt], a_base + 16 * SA + kt * 32);
        ldsm4(alo0[kt], a_base + ALO + kt * 32);
        ldsm4(alo1[kt], a_base + ALO + 16 * SA + kt * 32);
    }
    const int bn = 8 * (lane >> 4) + (lane & 7), bk8 = (lane >> 3) & 1;
    const uint32_t bh_base0 = sb + BH0 + bn * SA + bk8 * 16;
    const uint32_t bh_base1 = sb + BH1 + bn * SA + bk8 * 16;

    const int cell = 8 * w + (lane >> 2);
    float cs[4][2];
#pragma unroll
    for (int nt = 0; nt < 4; nt++) { cs[nt][0] = 0.f; cs[nt][1] = 0.f; }
    const int srow = tid >> 3, sch = tid & 7;
    const float* T0 = g_T0 + (size_t)dir * 128 * 256;

    for (int t = 0; t < Lseq; t++) {
        const int tcur = dir ? (Lseq - 1 - t) : t;
        const uint32_t bh_cur = (t & 1) ? bh_base1 : bh_base0;      // holds h(t-1)
        const uint32_t bwofs  = (t & 1) ? BH0 : BH1;                // epilogue target

        // y-store h(t-1) from current buffer (coalesced)
        if (t > 0) {
            int tprev = dir ? (Lseq - t) : (t - 1);
            uint32_t rofs = ((t & 1) ? BH1 : BH0) + srow * SA + sch * 16;
            *(uint4*)(g_y0 + ((size_t)tprev * Bsz + b0i + srow) * 128 + dir * 64 + sch * 8)
                = *(uint4*)(smem + rofs);
        }

        // token-table gather (fp32 exact; overlaps mma)
        float4 tv[4][2];
#pragma unroll
        for (int nt = 0; nt < 4; nt++)
#pragma unroll
            for (int hh = 0; hh < 2; hh++) {
                int bb = 8 * nt + 2 * (lane & 3) + hh;
                int tok = __ldg(&xtok[(b0i + bb) * Lseq + tcur]);
                tv[nt][hh] = *(const float4*)(T0 + ((size_t)tok * 64 + cell) * 4);
            }

        // D = Whi*h + Wlo*h
        float acc[2][4][4];
#pragma unroll
        for (int mt = 0; mt < 2; mt++)
#pragma unroll
            for (int nt = 0; nt < 4; nt++)
#pragma unroll
                for (int r = 0; r < 4; r++) acc[mt][nt][r] = 0.f;
#pragma unroll
        for (int kt = 0; kt < 4; kt++) {
            uint32_t bh0[4], bh1[4];
            ldsm4(bh0, bh_cur + kt * 32);
            ldsm4(bh1, bh_cur + 16 * SA + kt * 32);
            mmaf16(acc[0][0], ahi0[kt], bh0);     mmaf16(acc[0][0], alo0[kt], bh0);
            mmaf16(acc[0][1], ahi0[kt], bh0 + 2); mmaf16(acc[0][1], alo0[kt], bh0 + 2);
            mmaf16(acc[0][2], ahi0[kt], bh1);     mmaf16(acc[0][2], alo0[kt], bh1);
            mmaf16(acc[0][3], ahi0[kt], bh1 + 2); mmaf16(acc[0][3], alo0[kt], bh1 + 2);
            mmaf16(acc[1][0], ahi1[kt], bh0);     mmaf16(acc[1][0], alo1[kt], bh0);
            mmaf16(acc[1][1], ahi1[kt], bh0 + 2); mmaf16(acc[1][1], alo1[kt], bh0 + 2);
            mmaf16(acc[1][2], ahi1[kt], bh1);     mmaf16(acc[1][2], alo1[kt], bh1);
            mmaf16(acc[1][3], ahi1[kt], bh1 + 2); mmaf16(acc[1][3], alo1[kt], bh1 + 2);
        }

        // epilogue -> OTHER h buffer (no hazard with in-flight reads of current)
#pragma unroll
        for (int nt = 0; nt < 4; nt++)
#pragma unroll
            for (int hh = 0; hh < 2; hh++) {
                float iv = acc[0][nt][hh]     + tv[nt][hh].x;
                float fv = acc[0][nt][2 + hh] + tv[nt][hh].y;
                float gv = acc[1][nt][hh]     + tv[nt][hh].z;
                float ov = acc[1][nt][2 + hh] + tv[nt][hh].w;
                float c = sigf(fv) * cs[nt][hh] + sigf(iv) * tanha(gv);
                cs[nt][hh] = c;
                float h = sigf(ov) * tanha(c);
                int bb = 8 * nt + 2 * (lane & 3) + hh;
                *(__half*)(smem + bwofs + bb * SA + cell * 2) = __float2half_rn(h);
            }
        __syncthreads();   // h(t) visible for step t+1
    }
    { // flush last h: epilogue(255) wrote BH0
        int tprev = dir ? 0 : (Lseq - 1);
        *(uint4*)(g_y0 + ((size_t)tprev * Bsz + b0i + srow) * 128 + dir * 64 + sch * 8)
            = *(uint4*)(smem + BH0 + srow * SA + sch * 16);
    }
}

// ================= kernel 3: layer-1 LSTM =================
// K=192: x-part (y0, k 0..127) SINGLE pass (Whi only); h-part (k 128..191) 2-pass.
// Double-buffered x and h tiles, ONE barrier/step.
__global__ void __launch_bounds__(256, 1)
lstm1_kernel(const float* __restrict__ Wih1, const float* __restrict__ Whh1,
             const float* __restrict__ bias) {
    constexpr int SAW = 400;                  // A-hi row stride (192*2+16)
    constexpr int SH  = 144;                  // h / A-lo row stride (64*2+16)
    constexpr int SX  = 272;                  // x row stride (128*2+16)
    constexpr int AHI = 0;                    // [256][SAW]          102400
    constexpr int ALO = 256 * SAW;            // [256][SH] h-cols    36864 -> 139264
    constexpr int BX0 = ALO + 256 * SH;       // [32][SX]            8704  -> 147968
    constexpr int BX1 = BX0 + 32 * SX;        //                     8704  -> 156672
    constexpr int BH0 = BX1 + 32 * SX;        // [32][SH]            4608  -> 161280
    constexpr int BH1 = BH0 + 32 * SH;        //                     4608  -> 165888 total

    extern __shared__ __align__(16) char smem[];
    const uint32_t sb = s2u(smem);
    const int dir = blockIdx.y, b0i = blockIdx.x * NB;
    const int tid = threadIdx.x, lane = tid & 31, w = tid >> 5;

    // fill weights: A-hi full K; A-lo only h-columns (k 128..191)
    {
        const int m = tid;
        const int cellm = 8 * (m >> 5) + (m & 7), gate = (m >> 3) & 3;
        const int grow = dir * 256 + gate * 64 + cellm;
        const float* si = Wih1 + (size_t)grow * 128;
        const float* sh = Whh1 + (size_t)grow * 64;
        char* rowp = smem + m * SAW;
        for (int k = 0; k < 128; k++)
            *(__half*)(rowp + k * 2) = __float2half_rn(si[k]);
        char* lorp = smem + ALO + m * SH;
#pragma unroll 8
        for (int k = 0; k < 64; k++) {
            __half hi, lo; split2h(sh[k], hi, lo);
            *(__half*)(rowp + (128 + k) * 2) = hi;
            *(__half*)(lorp + k * 2) = lo;
        }
    }
    { // zero h buffer 0
        int row = tid >> 3, ch = tid & 7;
        *(uint4*)(smem + BH0 + row * SH + ch * 16) = make_uint4(0, 0, 0, 0);
    }
    // stage x(0) into BX0
    {
        int tn = dir ? (Lseq - 1) : 0;
        const int r0 = tid >> 4, c0 = tid & 15;
        *(uint4*)(smem + BX0 + r0 * SX + c0 * 16)
            = *(const uint4*)(g_y0 + ((size_t)tn * Bsz + b0i + r0) * 128 + c0 * 8);
        const int r1 = r0 + 16;
        *(uint4*)(smem + BX0 + r1 * SX + c0 * 16)
            = *(const uint4*)(g_y0 + ((size_t)tn * Bsz + b0i + r1) * 128 + c0 * 8);
    }
    __syncthreads();

    // A-hi fragments -> registers (12 kt covering K=192)
    const int lrow = ((lane >> 3) & 1) * 8 + (lane & 7);
    const int lk8  = lane >> 4;
    const uint32_t a_base = sb + (32 * w + lrow) * SAW + lk8 * 16;
    uint32_t ahi0[12][4], ahi1[12][4];
#pragma unroll
    for (int kt = 0; kt < 12; kt++) {
        ldsm4(ahi0[kt], a_base + kt * 32);
        ldsm4(ahi1[kt], a_base + 16 * SAW + kt * 32);
    }
    const uint32_t alo_base = sb + ALO + (32 * w + lrow) * SH + lk8 * 16;
    const int bn  = 8 * (lane >> 4) + (lane & 7);
    const int bk8 = (lane >> 3) & 1;
    const uint32_t bx_b0 = sb + BX0 + bn * SX + bk8 * 16;
    const uint32_t bx_b1 = sb + BX1 + bn * SX + bk8 * 16;
    const uint32_t bh_b0 = sb + BH0 + bn * SH + bk8 * 16;
    const uint32_t bh_b1 = sb + BH1 + bn * SH + bk8 * 16;

    const int cell = 8 * w + (lane >> 2);
    const float* bp = bias + dir * 512;
    const float bi_ = bp[cell]       + bp[256 + cell];
    const float bf_ = bp[64 + cell]  + bp[320 + cell];
    const float bg_ = bp[128 + cell] + bp[384 + cell];
    const float bo_ = bp[192 + cell] + bp[448 + cell];

    float cs[4][2];
#pragma unroll
    for (int nt = 0; nt < 4; nt++) { cs[nt][0] = 0.f; cs[nt][1] = 0.f; }
    const int r0 = tid >> 4, c0 = tid & 15, r1 = r0 + 16;

    for (int t = 0; t < Lseq; t++) {
        const uint32_t bx_cur = (t & 1) ? bx_b1 : bx_b0;
        const uint32_t bh_cur = (t & 1) ? bh_b1 : bh_b0;
        const uint32_t bhw    = (t & 1) ? BH0 : BH1;
        const uint32_t bxw    = (t & 1) ? BX0 : BX1;

        // prefetch x(t+1) into registers (overlaps mma)
        uint4 pf0, pf1;
        if (t + 1 < Lseq) {
            int tn = dir ? (Lseq - 2 - t) : (t + 1);
            pf0 = *(const uint4*)(g_y0 + ((size_t)tn * Bsz + b0i + r0) * 128 + c0 * 8);
            pf1 = *(const uint4*)(g_y0 + ((size_t)tn * Bsz + b0i + r1) * 128 + c0 * 8);
        }

        float acc[2][4][4];
#pragma unroll
        for (int mt = 0; mt < 2; mt++)
#pragma unroll
            for (int nt = 0; nt < 4; nt++)
#pragma unroll
                for (int r = 0; r < 4; r++) acc[mt][nt][r] = 0.f;

        // x-part: single pass (Whi only)
#pragma unroll
        for (int kt = 0; kt < 8; kt++) {
            uint32_t bx0[4], bx1[4];
            ldsm4(bx0, bx_cur + kt * 32);
            ldsm4(bx1, bx_cur + 16 * SX + kt * 32);
            mmaf16(acc[0][0], ahi0[kt], bx0);
            mmaf16(acc[0][1], ahi0[kt], bx0 + 2);
            mmaf16(acc[0][2], ahi0[kt], bx1);
            mmaf16(acc[0][3], ahi0[kt], bx1 + 2);
            mmaf16(acc[1][0], ahi1[kt], bx0);
            mmaf16(acc[1][1], ahi1[kt], bx0 + 2);
            mmaf16(acc[1][2], ahi1[kt], bx1);
            mmaf16(acc[1][3], ahi1[kt], bx1 + 2);
        }
        // h-part: 2-pass (Whi + Wlo)
#pragma unroll
        for (int kt = 8; kt < 12; kt++) {
            const int kh = kt - 8;
            uint32_t alo0[4], alo1[4], bh0[4], bh1[4];
            ldsm4(alo0, alo_base + kh * 32);
            ldsm4(alo1, alo_base + 16 * SH + kh * 32);
            ldsm4(bh0, bh_cur + kh * 32);
            ldsm4(bh1, bh_cur + 16 * SH + kh * 32);
            mmaf16(acc[0][0], ahi0[kt], bh0);     mmaf16(acc[0][0], alo0, bh0);
            mmaf16(acc[0][1], ahi0[kt], bh0 + 2); mmaf16(acc[0][1], alo0, bh0 + 2);
            mmaf16(acc[0][2], ahi0[kt], bh1);     mmaf16(acc[0][2], alo0, bh1);
            mmaf16(acc[0][3], ahi0[kt], bh1 + 2); mmaf16(acc[0][3], alo0, bh1 + 2);
            mmaf16(acc[1][0], ahi1[kt], bh0);     mmaf16(acc[1][0], alo1, bh0);
            mmaf16(acc[1][1], ahi1[kt], bh0 + 2); mmaf16(acc[1][1], alo1, bh0 + 2);
            mmaf16(acc[1][2], ahi1[kt], bh1);     mmaf16(acc[1][2], alo1, bh1);
            mmaf16(acc[1][3], ahi1[kt], bh1 + 2); mmaf16(acc[1][3], alo1, bh1 + 2);
        }

        // epilogue -> OTHER h buffer
#pragma unroll
        for (int nt = 0; nt < 4; nt++)
#pragma unroll
            for (int hh = 0; hh < 2; hh++) {
                int bb = 8 * nt + 2 * (lane & 3) + hh;
                float iv = acc[0][nt][hh]     + bi_;
                float fv = acc[0][nt][2 + hh] + bf_;
                float gv = acc[1][nt][hh]     + bg_;
                float ov = acc[1][nt][2 + hh] + bo_;
                float c = sigf(fv) * cs[nt][hh] + sigf(iv) * tanha(gv);
                cs[nt][hh] = c;
                float h = sigf(ov) * tanha(c);
                *(__half*)(smem + bhw + bb * SH + cell * 2) = __float2half_rn(h);
                if (t == Lseq - 1)
                    g_hfin[(b0i + bb) * 128 + dir * 64 + cell] = h;
            }

        // store prefetched x(t+1) -> OTHER x buffer
        if (t + 1 < Lseq) {
            *(uint4*)(smem + bxw + r0 * SX + c0 * 16) = pf0;
            *(uint4*)(smem + bxw + r1 * SX + c0 * 16) = pf1;
        }
        __syncthreads();   // h(t) + x(t+1) visible for next step
    }
}

// ================= kernel 4: MLP head =================
__global__ void __launch_bounds__(256)
head_kernel(const float* __restrict__ W1, const float* __restrict__ bf1,
            const float* __restrict__ W2, const float* __restrict__ bf2,
            float* __restrict__ out) {
    extern __shared__ float hs[];
    float* sW1 = hs;                           // [64][129]
    float* sh  = hs + 64 * 129;                // [32][129]
    float* sW2 = hs + 64 * 129 + 32 * 129;     // [64]
    float* sb1 = sW2 + 64;                     // [64]
    const int tid = threadIdx.x;
    const int b0 = blockIdx.x * 32;

    for (int i = tid; i < 64 * 128; i += 256) sW1[(i >> 7) * 129 + (i & 127)] = W1[i];
    for (int i = tid; i < 32 * 128; i += 256) sh[(i >> 7) * 129 + (i & 127)] = g_hfin[b0 * 128 + i];
    if (tid < 64) { sW2[tid] = W2[tid]; sb1[tid] = bf1[tid]; }
    __syncthreads();

    const int bi = tid >> 3, g8 = tid & 7;
    const float* hrow = sh + bi * 129;
    float part = 0.f;
#pragma unroll
    for (int jj = 0; jj < 8; jj++) {
        int j = g8 * 8 + jj;
        float z = sb1[j];
        const float* wrow = sW1 + j * 129;
#pragma unroll 16
        for (int k = 0; k < 128; k++) z += hrow[k] * wrow[k];
        part += fmaxf(z, 0.f) * sW2[j];
    }
#pragma unroll
    for (int o = 4; o; o >>= 1) part += __shfl_down_sync(0xffffffffu, part, o, 8);
    if (g8 == 0) out[b0 + bi] = part + bf2[0];
}

// ================= launch =================
extern "C" void kernel_launch(void* const* d_in, const int* in_sizes, int n_in,
                              void* d_out, int out_size) {
    const int*   x    = (const int*)  d_in[0];
    const float* emb  = (const float*)d_in[1];
    const float* Wih0 = (const float*)d_in[2];
    const float* Whh0 = (const float*)d_in[3];
    const float* b0   = (const float*)d_in[4];
    const float* Wih1 = (const float*)d_in[5];
    const float* Whh1 = (const float*)d_in[6];
    const float* b1   = (const float*)d_in[7];
    const float* W1   = (const float*)d_in[8];
    const float* bf1  = (const float*)d_in[9];
    const float* W2   = (const float*)d_in[10];
    const float* bf2  = (const float*)d_in[11];
    float* out = (float*)d_out;

    const int SM0 = 2 * 256 * 144 + 2 * 32 * 144;                       // 82944
    const int SM1 = 256 * 400 + 256 * 144 + 2 * 32 * 272 + 2 * 32 * 144; // 165888
    const int SMH = (64 * 129 + 32 * 129 + 128) * 4;
    cudaFuncSetAttribute(lstm0_kernel, cudaFuncAttributeMaxDynamicSharedMemorySize, SM0);
    cudaFuncSetAttribute(lstm1_kernel, cudaFuncAttributeMaxDynamicSharedMemorySize, SM1);
    cudaFuncSetAttribute(head_kernel,  cudaFuncAttributeMaxDynamicSharedMemorySize, SMH);

    table_kernel<<<dim3(128, 2), 256>>>(emb, Wih0, b0);
    lstm0_kernel<<<dim3(Bsz / NB, 2), 256, SM0>>>(x, Whh0);
    lstm1_kernel<<<dim3(Bsz / NB, 2), 256, SM1>>>(Wih1, Whh1, b1);
    head_kernel<<<64, 256, SMH>>>(W1, bf1, W2, bf2, out);
}

// round 13
// speedup vs baseline: 5.9401x; 1.0703x over previous
#include <cuda_runtime.h>
#include <cuda_fp16.h>
#include <cstdint>

#define Bsz   2048
#define Lseq  256

// ---------------- device scratch ----------------
__device__ float g_T0[2 * 128 * 256];                 // token table [dir][tok][cell][gate4] fp32
__device__ __half g_y0[(size_t)Lseq * Bsz * 128];     // layer-0 output fp16 [t][b][128]
__device__ float g_hfin[Bsz * 128];                   // layer-1 final hidden [b][hf|hb]

// ---------------- helpers ----------------
__device__ __forceinline__ uint32_t s2u(const void* p) {
    uint32_t a;
    asm("{ .reg .u64 t; cvta.to.shared.u64 t, %1; cvt.u32.u64 %0, t; }" : "=r"(a) : "l"(p));
    return a;
}
__device__ __forceinline__ float tanha(float x) {
    float y; asm("tanh.approx.f32 %0, %1;" : "=f"(y) : "f"(x)); return y;
}
__device__ __forceinline__ float sigf(float x) { return fmaf(0.5f, tanha(0.5f * x), 0.5f); }

__device__ __forceinline__ void ldsm4(uint32_t* r, uint32_t addr) {
    asm volatile("ldmatrix.sync.aligned.m8n8.x4.shared.b16 {%0,%1,%2,%3}, [%4];"
        : "=r"(r[0]), "=r"(r[1]), "=r"(r[2]), "=r"(r[3]) : "r"(addr));
}
__device__ __forceinline__ void mmaf16(float* d, const uint32_t* a, const uint32_t* b) {
    asm volatile("mma.sync.aligned.m16n8k16.row.col.f32.f16.f16.f32 "
        "{%0,%1,%2,%3}, {%4,%5,%6,%7}, {%8,%9}, {%0,%1,%2,%3};"
        : "+f"(d[0]), "+f"(d[1]), "+f"(d[2]), "+f"(d[3])
        : "r"(a[0]), "r"(a[1]), "r"(a[2]), "r"(a[3]), "r"(b[0]), "r"(b[1]));
}
__device__ __forceinline__ void split2h(float v, __half& hi, __half& lo) {
    hi = __float2half_rn(v);
    lo = __float2half_rn(v - __half2float(hi));
}

// ================= kernel 1: layer-0 token table (fp32 exact) =================
__global__ void table_kernel(const float* __restrict__ emb,
                             const float* __restrict__ Wih0,
                             const float* __restrict__ b0) {
    const int v = blockIdx.x, dir = blockIdx.y, tid = threadIdx.x;
    const int cell = tid >> 2, gate = tid & 3;
    __shared__ float se[64];
    if (tid < 64) se[tid] = emb[v * 64 + tid];
    __syncthreads();
    const float* wrow = Wih0 + (size_t)(dir * 256 + gate * 64 + cell) * 64;
    float s = b0[dir * 512 + gate * 64 + cell] + b0[dir * 512 + 256 + gate * 64 + cell];
#pragma unroll
    for (int k = 0; k < 64; k++) s += se[k] * wrow[k];
    g_T0[((size_t)(dir * 128 + v) * 64 + cell) * 4 + gate] = s;
}

// ================= kernel 2: layer-0 LSTM =================
// NB=16, 2 CTAs/SM. K=64 h-only (x via exact table), fp16 2-pass weights.
// A-hi in regs, A-lo via LDSM. Double-buffered h, ONE barrier/step.
// Thread (w,lane): cell = 8w+(lane>>2); batches 8*nt+2*(lane&3)+{0,1}, nt<2.
__global__ void __launch_bounds__(256, 2)
lstm0_kernel(const int* __restrict__ xtok, const float* __restrict__ Whh0) {
    constexpr int SA  = 144;                   // 64*2 + 16
    constexpr int ALO = 256 * SA;              // 36864
    constexpr int BH0 = 2 * 256 * SA;          // 73728
    constexpr int BH1 = BH0 + 16 * SA;         // 76032 (total 78336)
    extern __shared__ __align__(16) char smem[];
    const uint32_t sb = s2u(smem);
    const int dir = blockIdx.y, b0i = blockIdx.x * 16;
    const int tid = threadIdx.x, lane = tid & 31, w = tid >> 5;

    // fill split Whh (hi, lo), permuted rows
    {
        const int m = tid;
        const int cellm = 8 * (m >> 5) + (m & 7), gate = (m >> 3) & 3;
        const float* sh = Whh0 + (size_t)(dir * 256 + gate * 64 + cellm) * 64;
        char* rowp = smem + m * SA;
#pragma unroll 8
        for (int k = 0; k < 64; k++) {
            __half hi, lo; split2h(sh[k], hi, lo);
            *(__half*)(rowp + k * 2) = hi;
            *(__half*)(rowp + ALO + k * 2) = lo;
        }
    }
    if (tid < 128) { // zero h buffer 0 (16 rows x 8 chunks)
        int row = tid >> 3, ch = tid & 7;
        *(uint4*)(smem + BH0 + row * SA + ch * 16) = make_uint4(0, 0, 0, 0);
    }
    __syncthreads();

    // A-hi fragments -> registers
    const int lrow = ((lane >> 3) & 1) * 8 + (lane & 7);
    const int lk8 = lane >> 4;
    const uint32_t a_base = sb + (32 * w + lrow) * SA + lk8 * 16;
    const uint32_t alo_base = a_base + ALO;
    uint32_t ahi0[4][4], ahi1[4][4];
#pragma unroll
    for (int kt = 0; kt < 4; kt++) {
        ldsm4(ahi0[kt], a_base + kt * 32);
        ldsm4(ahi1[kt], a_base + 16 * SA + kt * 32);
    }
    const int bn = 8 * (lane >> 4) + (lane & 7), bk8 = (lane >> 3) & 1;
    const uint32_t bh_base0 = sb + BH0 + bn * SA + bk8 * 16;
    const uint32_t bh_base1 = sb + BH1 + bn * SA + bk8 * 16;

    const int cell = 8 * w + (lane >> 2);
    float cs[2][2];
    cs[0][0] = cs[0][1] = cs[1][0] = cs[1][1] = 0.f;
    const int srow = (tid >> 3) & 15, sch = tid & 7;
    const float* T0 = g_T0 + (size_t)dir * 128 * 256;

    for (int t = 0; t < Lseq; t++) {
        const int tcur = dir ? (Lseq - 1 - t) : t;
        const uint32_t bh_cur = (t & 1) ? bh_base1 : bh_base0;      // holds h(t-1)
        const uint32_t bwofs  = (t & 1) ? BH0 : BH1;                // epilogue target

        // y-store h(t-1)
        if (t > 0 && tid < 128) {
            int tprev = dir ? (Lseq - t) : (t - 1);
            uint32_t rofs = ((t & 1) ? BH1 : BH0) + srow * SA + sch * 16;
            *(uint4*)(g_y0 + ((size_t)tprev * Bsz + b0i + srow) * 128 + dir * 64 + sch * 8)
                = *(uint4*)(smem + rofs);
        }

        // token-table gather (fp32 exact; overlaps mma)
        float4 tv[2][2];
#pragma unroll
        for (int nt = 0; nt < 2; nt++)
#pragma unroll
            for (int hh = 0; hh < 2; hh++) {
                int bb = 8 * nt + 2 * (lane & 3) + hh;
                int tok = __ldg(&xtok[(b0i + bb) * Lseq + tcur]);
                tv[nt][hh] = *(const float4*)(T0 + ((size_t)tok * 64 + cell) * 4);
            }

        // D = Whi*h + Wlo*h
        float acc[2][2][4];
#pragma unroll
        for (int mt = 0; mt < 2; mt++)
#pragma unroll
            for (int nt = 0; nt < 2; nt++)
#pragma unroll
                for (int r = 0; r < 4; r++) acc[mt][nt][r] = 0.f;
#pragma unroll
        for (int kt = 0; kt < 4; kt++) {
            uint32_t alo0[4], alo1[4], bh0[4];
            ldsm4(alo0, alo_base + kt * 32);
            ldsm4(alo1, alo_base + 16 * SA + kt * 32);
            ldsm4(bh0, bh_cur + kt * 32);
            mmaf16(acc[0][0], ahi0[kt], bh0);     mmaf16(acc[0][0], alo0, bh0);
            mmaf16(acc[0][1], ahi0[kt], bh0 + 2); mmaf16(acc[0][1], alo0, bh0 + 2);
            mmaf16(acc[1][0], ahi1[kt], bh0);     mmaf16(acc[1][0], alo1, bh0);
            mmaf16(acc[1][1], ahi1[kt], bh0 + 2); mmaf16(acc[1][1], alo1, bh0 + 2);
        }

        // epilogue -> OTHER h buffer
#pragma unroll
        for (int nt = 0; nt < 2; nt++)
#pragma unroll
            for (int hh = 0; hh < 2; hh++) {
                float iv = acc[0][nt][hh]     + tv[nt][hh].x;
                float fv = acc[0][nt][2 + hh] + tv[nt][hh].y;
                float gv = acc[1][nt][hh]     + tv[nt][hh].z;
                float ov = acc[1][nt][2 + hh] + tv[nt][hh].w;
                float c = sigf(fv) * cs[nt][hh] + sigf(iv) * tanha(gv);
                cs[nt][hh] = c;
                float h = sigf(ov) * tanha(c);
                int bb = 8 * nt + 2 * (lane & 3) + hh;
                *(__half*)(smem + bwofs + bb * SA + cell * 2) = __float2half_rn(h);
            }
        __syncthreads();   // h(t) visible for step t+1
    }
    if (tid < 128) { // flush last h: epilogue(255) wrote BH0
        int tprev = dir ? 0 : (Lseq - 1);
        *(uint4*)(g_y0 + ((size_t)tprev * Bsz + b0i + srow) * 128 + dir * 64 + sch * 8)
            = *(uint4*)(smem + BH0 + srow * SA + sch * 16);
    }
}

// ================= kernel 3: layer-1 LSTM (round-10 proven version) =================
// NB=32. x-part (y0) single-pass, h-part 2-pass. Double-buffered x and h,
// register prefetch of x(t+1), ONE barrier/step.
__global__ void __launch_bounds__(256, 1)
lstm1_kernel(const float* __restrict__ Wih1, const float* __restrict__ Whh1,
             const float* __restrict__ bias) {
    constexpr int SAW = 400;                  // A-hi row stride (192*2+16)
    constexpr int SH  = 144;                  // h / A-lo row stride
    constexpr int SX  = 272;                  // x row stride
    constexpr int ALO = 256 * SAW;            // 102400
    constexpr int BX0 = ALO + 256 * SH;       // 139264
    constexpr int BX1 = BX0 + 32 * SX;        // 147968
    constexpr int BH0 = BX1 + 32 * SX;        // 156672
    constexpr int BH1 = BH0 + 32 * SH;        // 161280 (total 165888)

    extern __shared__ __align__(16) char smem[];
    const uint32_t sb = s2u(smem);
    const int dir = blockIdx.y, b0i = blockIdx.x * 32;
    const int tid = threadIdx.x, lane = tid & 31, w = tid >> 5;

    // fill weights: A-hi full K; A-lo only h-cols
    {
        const int m = tid;
        const int cellm = 8 * (m >> 5) + (m & 7), gate = (m >> 3) & 3;
        const int grow = dir * 256 + gate * 64 + cellm;
        const float* si = Wih1 + (size_t)grow * 128;
        const float* sh = Whh1 + (size_t)grow * 64;
        char* rowp = smem + m * SAW;
        for (int k = 0; k < 128; k++)
            *(__half*)(rowp + k * 2) = __float2half_rn(si[k]);
        char* lorp = smem + ALO + m * SH;
#pragma unroll 8
        for (int k = 0; k < 64; k++) {
            __half hi, lo; split2h(sh[k], hi, lo);
            *(__half*)(rowp + (128 + k) * 2) = hi;
            *(__half*)(lorp + k * 2) = lo;
        }
    }
    { // zero h buffer 0
        int row = tid >> 3, ch = tid & 7;
        *(uint4*)(smem + BH0 + row * SH + ch * 16) = make_uint4(0, 0, 0, 0);
    }
    // stage x(0) into BX0
    const int r0 = tid >> 4, c0 = tid & 15, r1 = r0 + 16;
    {
        int tn = dir ? (Lseq - 1) : 0;
        *(uint4*)(smem + BX0 + r0 * SX + c0 * 16)
            = *(const uint4*)(g_y0 + ((size_t)tn * Bsz + b0i + r0) * 128 + c0 * 8);
        *(uint4*)(smem + BX0 + r1 * SX + c0 * 16)
            = *(const uint4*)(g_y0 + ((size_t)tn * Bsz + b0i + r1) * 128 + c0 * 8);
    }
    __syncthreads();

    // A-hi fragments -> registers (12 kt covering K=192)
    const int lrow = ((lane >> 3) & 1) * 8 + (lane & 7);
    const int lk8  = lane >> 4;
    const uint32_t a_base = sb + (32 * w + lrow) * SAW + lk8 * 16;
    uint32_t ahi0[12][4], ahi1[12][4];
#pragma unroll
    for (int kt = 0; kt < 12; kt++) {
        ldsm4(ahi0[kt], a_base + kt * 32);
        ldsm4(ahi1[kt], a_base + 16 * SAW + kt * 32);
    }
    const uint32_t alo_base = sb + ALO + (32 * w + lrow) * SH + lk8 * 16;
    const int bn  = 8 * (lane >> 4) + (lane & 7);
    const int bk8 = (lane >> 3) & 1;
    const uint32_t bx_b0 = sb + BX0 + bn * SX + bk8 * 16;
    const uint32_t bx_b1 = sb + BX1 + bn * SX + bk8 * 16;
    const uint32_t bh_b0 = sb + BH0 + bn * SH + bk8 * 16;
    const uint32_t bh_b1 = sb + BH1 + bn * SH + bk8 * 16;

    const int cell = 8 * w + (lane >> 2);
    const float* bp = bias + dir * 512;
    const float bi_ = bp[cell]       + bp[256 + cell];
    const float bf_ = bp[64 + cell]  + bp[320 + cell];
    const float bg_ = bp[128 + cell] + bp[384 + cell];
    const float bo_ = bp[192 + cell] + bp[448 + cell];

    float cs[4][2];
#pragma unroll
    for (int nt = 0; nt < 4; nt++) { cs[nt][0] = 0.f; cs[nt][1] = 0.f; }

    for (int t = 0; t < Lseq; t++) {
        const uint32_t bx_cur = (t & 1) ? bx_b1 : bx_b0;
        const uint32_t bh_cur = (t & 1) ? bh_b1 : bh_b0;
        const uint32_t bhw    = (t & 1) ? BH0 : BH1;
        const uint32_t bxw    = (t & 1) ? BX0 : BX1;

        // prefetch x(t+1) into registers (overlaps mma)
        uint4 pf0, pf1;
        if (t + 1 < Lseq) {
            int tn = dir ? (Lseq - 2 - t) : (t + 1);
            pf0 = *(const uint4*)(g_y0 + ((size_t)tn * Bsz + b0i + r0) * 128 + c0 * 8);
            pf1 = *(const uint4*)(g_y0 + ((size_t)tn * Bsz + b0i + r1) * 128 + c0 * 8);
        }

        float acc[2][4][4];
#pragma unroll
        for (int mt = 0; mt < 2; mt++)
#pragma unroll
            for (int nt = 0; nt < 4; nt++)
#pragma unroll
                for (int r = 0; r < 4; r++) acc[mt][nt][r] = 0.f;

        // x-part: single pass (Whi only)
#pragma unroll
        for (int kt = 0; kt < 8; kt++) {
            uint32_t bx0[4], bx1[4];
            ldsm4(bx0, bx_cur + kt * 32);
            ldsm4(bx1, bx_cur + 16 * SX + kt * 32);
            mmaf16(acc[0][0], ahi0[kt], bx0);
            mmaf16(acc[0][1], ahi0[kt], bx0 + 2);
            mmaf16(acc[0][2], ahi0[kt], bx1);
            mmaf16(acc[0][3], ahi0[kt], bx1 + 2);
            mmaf16(acc[1][0], ahi1[kt], bx0);
            mmaf16(acc[1][1], ahi1[kt], bx0 + 2);
            mmaf16(acc[1][2], ahi1[kt], bx1);
            mmaf16(acc[1][3], ahi1[kt], bx1 + 2);
        }
        // h-part: 2-pass (Whi + Wlo)
#pragma unroll
        for (int kt = 8; kt < 12; kt++) {
            const int kh = kt - 8;
            uint32_t alo0[4], alo1[4], bh0[4], bh1[4];
            ldsm4(alo0, alo_base + kh * 32);
            ldsm4(alo1, alo_base + 16 * SH + kh * 32);
            ldsm4(bh0, bh_cur + kh * 32);
            ldsm4(bh1, bh_cur + 16 * SH + kh * 32);
            mmaf16(acc[0][0], ahi0[kt], bh0);     mmaf16(acc[0][0], alo0, bh0);
            mmaf16(acc[0][1], ahi0[kt], bh0 + 2); mmaf16(acc[0][1], alo0, bh0 + 2);
            mmaf16(acc[0][2], ahi0[kt], bh1);     mmaf16(acc[0][2], alo0, bh1);
            mmaf16(acc[0][3], ahi0[kt], bh1 + 2); mmaf16(acc[0][3], alo0, bh1 + 2);
            mmaf16(acc[1][0], ahi1[kt], bh0);     mmaf16(acc[1][0], alo1, bh0);
            mmaf16(acc[1][1], ahi1[kt], bh0 + 2); mmaf16(acc[1][1], alo1, bh0 + 2);
            mmaf16(acc[1][2], ahi1[kt], bh1);     mmaf16(acc[1][2], alo1, bh1);
            mmaf16(acc[1][3], ahi1[kt], bh1 + 2); mmaf16(acc[1][3], alo1, bh1 + 2);
        }

        // epilogue -> OTHER h buffer
#pragma unroll
        for (int nt = 0; nt < 4; nt++)
#pragma unroll
            for (int hh = 0; hh < 2; hh++) {
                int bb = 8 * nt + 2 * (lane & 3) + hh;
                float iv = acc[0][nt][hh]     + bi_;
                float fv = acc[0][nt][2 + hh] + bf_;
                float gv = acc[1][nt][hh]     + bg_;
                float ov = acc[1][nt][2 + hh] + bo_;
                float c = sigf(fv) * cs[nt][hh] + sigf(iv) * tanha(gv);
                cs[nt][hh] = c;
                float h = sigf(ov) * tanha(c);
                *(__half*)(smem + bhw + bb * SH + cell * 2) = __float2half_rn(h);
                if (t == Lseq - 1)
                    g_hfin[(b0i + bb) * 128 + dir * 64 + cell] = h;
            }

        // store prefetched x(t+1) -> OTHER x buffer
        if (t + 1 < Lseq) {
            *(uint4*)(smem + bxw + r0 * SX + c0 * 16) = pf0;
            *(uint4*)(smem + bxw + r1 * SX + c0 * 16) = pf1;
        }
        __syncthreads();   // h(t) + x(t+1) visible for next step
    }
}

// ================= kernel 4: MLP head =================
__global__ void __launch_bounds__(256)
head_kernel(const float* __restrict__ W1, const float* __restrict__ bf1,
            const float* __restrict__ W2, const float* __restrict__ bf2,
            float* __restrict__ out) {
    extern __shared__ float hs[];
    float* sW1 = hs;                           // [64][129]
    float* sh  = hs + 64 * 129;                // [32][129]
    float* sW2 = hs + 64 * 129 + 32 * 129;     // [64]
    float* sb1 = sW2 + 64;                     // [64]
    const int tid = threadIdx.x;
    const int b0 = blockIdx.x * 32;

    for (int i = tid; i < 64 * 128; i += 256) sW1[(i >> 7) * 129 + (i & 127)] = W1[i];
    for (int i = tid; i < 32 * 128; i += 256) sh[(i >> 7) * 129 + (i & 127)] = g_hfin[b0 * 128 + i];
    if (tid < 64) { sW2[tid] = W2[tid]; sb1[tid] = bf1[tid]; }
    __syncthreads();

    const int bi = tid >> 3, g8 = tid & 7;
    const float* hrow = sh + bi * 129;
    float part = 0.f;
#pragma unroll
    for (int jj = 0; jj < 8; jj++) {
        int j = g8 * 8 + jj;
        float z = sb1[j];
        const float* wrow = sW1 + j * 129;
#pragma unroll 16
        for (int k = 0; k < 128; k++) z += hrow[k] * wrow[k];
        part += fmaxf(z, 0.f) * sW2[j];
    }
#pragma unroll
    for (int o = 4; o; o >>= 1) part += __shfl_down_sync(0xffffffffu, part, o, 8);
    if (g8 == 0) out[b0 + bi] = part + bf2[0];
}

// ================= launch =================
extern "C" void kernel_launch(void* const* d_in, const int* in_sizes, int n_in,
                              void* d_out, int out_size) {
    const int*   x    = (const int*)  d_in[0];
    const float* emb  = (const float*)d_in[1];
    const float* Wih0 = (const float*)d_in[2];
    const float* Whh0 = (const float*)d_in[3];
    const float* b0   = (const float*)d_in[4];
    const float* Wih1 = (const float*)d_in[5];
    const float* Whh1 = (const float*)d_in[6];
    const float* b1   = (const float*)d_in[7];
    const float* W1   = (const float*)d_in[8];
    const float* bf1  = (const float*)d_in[9];
    const float* W2   = (const float*)d_in[10];
    const float* bf2  = (const float*)d_in[11];
    float* out = (float*)d_out;

    const int SM0 = 2 * 256 * 144 + 2 * 16 * 144;                        // 78336
    const int SM1 = 256 * 400 + 256 * 144 + 2 * 32 * 272 + 2 * 32 * 144; // 165888
    const int SMH = (64 * 129 + 32 * 129 + 128) * 4;
    cudaFuncSetAttribute(lstm0_kernel, cudaFuncAttributeMaxDynamicSharedMemorySize, SM0);
    cudaFuncSetAttribute(lstm1_kernel, cudaFuncAttributeMaxDynamicSharedMemorySize, SM1);
    cudaFuncSetAttribute(head_kernel,  cudaFuncAttributeMaxDynamicSharedMemorySize, SMH);

    table_kernel<<<dim3(128, 2), 256>>>(emb, Wih0, b0);
    lstm0_kernel<<<dim3(Bsz / 16, 2), 256, SM0>>>(x, Whh0);
    lstm1_kernel<<<dim3(Bsz / 32, 2), 256, SM1>>>(Wih1, Whh1, b1);
    head_kernel<<<64, 256, SMH>>>(W1, bf1, W2, bf2, out);
}

// round 14
// speedup vs baseline: 6.4758x; 1.0902x over previous
#include <cuda_runtime.h>
#include <cuda_fp16.h>
#include <cstdint>

#define Bsz   2048
#define Lseq  256

// ---------------- device scratch ----------------
__device__ float g_T0[2 * 128 * 256];                 // token table [dir][tok][cell][gate4] fp32
__device__ __half g_y0[(size_t)Lseq * Bsz * 128];     // layer-0 output fp16 [t][b][128]
__device__ float g_hfin[Bsz * 128];                   // layer-1 final hidden [b][hf|hb]

// ---------------- helpers ----------------
__device__ __forceinline__ uint32_t s2u(const void* p) {
    uint32_t a;
    asm("{ .reg .u64 t; cvta.to.shared.u64 t, %1; cvt.u32.u64 %0, t; }" : "=r"(a) : "l"(p));
    return a;
}
__device__ __forceinline__ float tanha(float x) {
    float y; asm("tanh.approx.f32 %0, %1;" : "=f"(y) : "f"(x)); return y;
}
__device__ __forceinline__ float sigf(float x) { return fmaf(0.5f, tanha(0.5f * x), 0.5f); }

__device__ __forceinline__ void ldsm4(uint32_t* r, uint32_t addr) {
    asm volatile("ldmatrix.sync.aligned.m8n8.x4.shared.b16 {%0,%1,%2,%3}, [%4];"
        : "=r"(r[0]), "=r"(r[1]), "=r"(r[2]), "=r"(r[3]) : "r"(addr));
}
__device__ __forceinline__ void mmaf16(float* d, const uint32_t* a, const uint32_t* b) {
    asm volatile("mma.sync.aligned.m16n8k16.row.col.f32.f16.f16.f32 "
        "{%0,%1,%2,%3}, {%4,%5,%6,%7}, {%8,%9}, {%0,%1,%2,%3};"
        : "+f"(d[0]), "+f"(d[1]), "+f"(d[2]), "+f"(d[3])
        : "r"(a[0]), "r"(a[1]), "r"(a[2]), "r"(a[3]), "r"(b[0]), "r"(b[1]));
}
__device__ __forceinline__ void split2h(float v, __half& hi, __half& lo) {
    hi = __float2half_rn(v);
    lo = __float2half_rn(v - __half2float(hi));
}

// ================= kernel 1: layer-0 token table (fp32 exact) =================
__global__ void table_kernel(const float* __restrict__ emb,
                             const float* __restrict__ Wih0,
                             const float* __restrict__ b0) {
    const int v = blockIdx.x, dir = blockIdx.y, tid = threadIdx.x;
    const int cell = tid >> 2, gate = tid & 3;
    __shared__ float se[64];
    if (tid < 64) se[tid] = emb[v * 64 + tid];
    __syncthreads();
    const float* wrow = Wih0 + (size_t)(dir * 256 + gate * 64 + cell) * 64;
    float s = b0[dir * 512 + gate * 64 + cell] + b0[dir * 512 + 256 + gate * 64 + cell];
#pragma unroll
    for (int k = 0; k < 64; k++) s += se[k] * wrow[k];
    g_T0[((size_t)(dir * 128 + v) * 64 + cell) * 4 + gate] = s;
}

// ================= kernel 2: layer-0 LSTM (unchanged from round 13) =================
// NB=16, 2 CTAs/SM. K=64 h-only (x via exact table), fp16 2-pass weights.
__global__ void __launch_bounds__(256, 2)
lstm0_kernel(const int* __restrict__ xtok, const float* __restrict__ Whh0) {
    constexpr int SA  = 144;                   // 64*2 + 16
    constexpr int ALO = 256 * SA;              // 36864
    constexpr int BH0 = 2 * 256 * SA;          // 73728
    constexpr int BH1 = BH0 + 16 * SA;         // 76032 (total 78336)
    extern __shared__ __align__(16) char smem[];
    const uint32_t sb = s2u(smem);
    const int dir = blockIdx.y, b0i = blockIdx.x * 16;
    const int tid = threadIdx.x, lane = tid & 31, w = tid >> 5;

    {
        const int m = tid;
        const int cellm = 8 * (m >> 5) + (m & 7), gate = (m >> 3) & 3;
        const float* sh = Whh0 + (size_t)(dir * 256 + gate * 64 + cellm) * 64;
        char* rowp = smem + m * SA;
#pragma unroll 8
        for (int k = 0; k < 64; k++) {
            __half hi, lo; split2h(sh[k], hi, lo);
            *(__half*)(rowp + k * 2) = hi;
            *(__half*)(rowp + ALO + k * 2) = lo;
        }
    }
    if (tid < 128) {
        int row = tid >> 3, ch = tid & 7;
        *(uint4*)(smem + BH0 + row * SA + ch * 16) = make_uint4(0, 0, 0, 0);
    }
    __syncthreads();

    const int lrow = ((lane >> 3) & 1) * 8 + (lane & 7);
    const int lk8 = lane >> 4;
    const uint32_t a_base = sb + (32 * w + lrow) * SA + lk8 * 16;
    const uint32_t alo_base = a_base + ALO;
    uint32_t ahi0[4][4], ahi1[4][4];
#pragma unroll
    for (int kt = 0; kt < 4; kt++) {
        ldsm4(ahi0[kt], a_base + kt * 32);
        ldsm4(ahi1[kt], a_base + 16 * SA + kt * 32);
    }
    const int bn = 8 * (lane >> 4) + (lane & 7), bk8 = (lane >> 3) & 1;
    const uint32_t bh_base0 = sb + BH0 + bn * SA + bk8 * 16;
    const uint32_t bh_base1 = sb + BH1 + bn * SA + bk8 * 16;

    const int cell = 8 * w + (lane >> 2);
    float cs[2][2];
    cs[0][0] = cs[0][1] = cs[1][0] = cs[1][1] = 0.f;
    const int srow = (tid >> 3) & 15, sch = tid & 7;
    const float* T0 = g_T0 + (size_t)dir * 128 * 256;

    for (int t = 0; t < Lseq; t++) {
        const int tcur = dir ? (Lseq - 1 - t) : t;
        const uint32_t bh_cur = (t & 1) ? bh_base1 : bh_base0;
        const uint32_t bwofs  = (t & 1) ? BH0 : BH1;

        if (t > 0 && tid < 128) {
            int tprev = dir ? (Lseq - t) : (t - 1);
            uint32_t rofs = ((t & 1) ? BH1 : BH0) + srow * SA + sch * 16;
            *(uint4*)(g_y0 + ((size_t)tprev * Bsz + b0i + srow) * 128 + dir * 64 + sch * 8)
                = *(uint4*)(smem + rofs);
        }

        float4 tv[2][2];
#pragma unroll
        for (int nt = 0; nt < 2; nt++)
#pragma unroll
            for (int hh = 0; hh < 2; hh++) {
                int bb = 8 * nt + 2 * (lane & 3) + hh;
                int tok = __ldg(&xtok[(b0i + bb) * Lseq + tcur]);
                tv[nt][hh] = *(const float4*)(T0 + ((size_t)tok * 64 + cell) * 4);
            }

        float acc[2][2][4];
#pragma unroll
        for (int mt = 0; mt < 2; mt++)
#pragma unroll
            for (int nt = 0; nt < 2; nt++)
#pragma unroll
                for (int r = 0; r < 4; r++) acc[mt][nt][r] = 0.f;
#pragma unroll
        for (int kt = 0; kt < 4; kt++) {
            uint32_t alo0[4], alo1[4], bh0[4];
            ldsm4(alo0, alo_base + kt * 32);
            ldsm4(alo1, alo_base + 16 * SA + kt * 32);
            ldsm4(bh0, bh_cur + kt * 32);
            mmaf16(acc[0][0], ahi0[kt], bh0);     mmaf16(acc[0][0], alo0, bh0);
            mmaf16(acc[0][1], ahi0[kt], bh0 + 2); mmaf16(acc[0][1], alo0, bh0 + 2);
            mmaf16(acc[1][0], ahi1[kt], bh0);     mmaf16(acc[1][0], alo1, bh0);
            mmaf16(acc[1][1], ahi1[kt], bh0 + 2); mmaf16(acc[1][1], alo1, bh0 + 2);
        }

#pragma unroll
        for (int nt = 0; nt < 2; nt++)
#pragma unroll
            for (int hh = 0; hh < 2; hh++) {
                float iv = acc[0][nt][hh]     + tv[nt][hh].x;
                float fv = acc[0][nt][2 + hh] + tv[nt][hh].y;
                float gv = acc[1][nt][hh]     + tv[nt][hh].z;
                float ov = acc[1][nt][2 + hh] + tv[nt][hh].w;
                float c = sigf(fv) * cs[nt][hh] + sigf(iv) * tanha(gv);
                cs[nt][hh] = c;
                float h = sigf(ov) * tanha(c);
                int bb = 8 * nt + 2 * (lane & 3) + hh;
                *(__half*)(smem + bwofs + bb * SA + cell * 2) = __float2half_rn(h);
            }
        __syncthreads();
    }
    if (tid < 128) {
        int tprev = dir ? 0 : (Lseq - 1);
        *(uint4*)(g_y0 + ((size_t)tprev * Bsz + b0i + srow) * 128 + dir * 64 + sch * 8)
            = *(uint4*)(smem + BH0 + srow * SA + sch * 16);
    }
}

// ================= kernel 3: layer-1 LSTM =================
// NB=32. ALL weights fp16 hi-only (x AND h single-pass). x-mma pipelined ONE
// step ahead reusing the SAME accumulator (register-lean). x staged 2-deep,
// double-buffered h, ONE barrier/step.
__global__ void __launch_bounds__(256, 1)
lstm1_kernel(const float* __restrict__ Wih1, const float* __restrict__ Whh1,
             const float* __restrict__ bias) {
    constexpr int SAW = 400;                  // A-hi row stride (192*2+16)
    constexpr int SH  = 144;                  // h row stride
    constexpr int SX  = 272;                  // x row stride
    constexpr int BX0 = 256 * SAW;            // 102400
    constexpr int BX1 = BX0 + 32 * SX;        // 111104
    constexpr int BH0 = BX1 + 32 * SX;        // 119808
    constexpr int BH1 = BH0 + 32 * SH;        // 124416 (total 129024)

    extern __shared__ __align__(16) char smem[];
    const uint32_t sb = s2u(smem);
    const int dir = blockIdx.y, b0i = blockIdx.x * 32;
    const int tid = threadIdx.x, lane = tid & 31, w = tid >> 5;

    // fill weights: A-hi full K (hi only), permuted rows
    {
        const int m = tid;
        const int cellm = 8 * (m >> 5) + (m & 7), gate = (m >> 3) & 3;
        const int grow = dir * 256 + gate * 64 + cellm;
        const float* si = Wih1 + (size_t)grow * 128;
        const float* sh = Whh1 + (size_t)grow * 64;
        char* rowp = smem + m * SAW;
        for (int k = 0; k < 128; k++)
            *(__half*)(rowp + k * 2) = __float2half_rn(si[k]);
#pragma unroll 8
        for (int k = 0; k < 64; k++)
            *(__half*)(rowp + (128 + k) * 2) = __float2half_rn(sh[k]);
    }
    { // zero h buffer 0
        int row = tid >> 3, ch = tid & 7;
        *(uint4*)(smem + BH0 + row * SH + ch * 16) = make_uint4(0, 0, 0, 0);
    }
    // stage x(0) -> BX0, x(1) -> BX1 (2-deep)
    const int r0 = tid >> 4, c0 = tid & 15, r1 = r0 + 16;
    {
        int t0n = dir ? (Lseq - 1) : 0;
        int t1n = dir ? (Lseq - 2) : 1;
        *(uint4*)(smem + BX0 + r0 * SX + c0 * 16)
            = *(const uint4*)(g_y0 + ((size_t)t0n * Bsz + b0i + r0) * 128 + c0 * 8);
        *(uint4*)(smem + BX0 + r1 * SX + c0 * 16)
            = *(const uint4*)(g_y0 + ((size_t)t0n * Bsz + b0i + r1) * 128 + c0 * 8);
        *(uint4*)(smem + BX1 + r0 * SX + c0 * 16)
            = *(const uint4*)(g_y0 + ((size_t)t1n * Bsz + b0i + r0) * 128 + c0 * 8);
        *(uint4*)(smem + BX1 + r1 * SX + c0 * 16)
            = *(const uint4*)(g_y0 + ((size_t)t1n * Bsz + b0i + r1) * 128 + c0 * 8);
    }
    __syncthreads();

    // A-hi fragments -> registers (12 kt covering K=192)
    const int lrow = ((lane >> 3) & 1) * 8 + (lane & 7);
    const int lk8  = lane >> 4;
    const uint32_t a_base = sb + (32 * w + lrow) * SAW + lk8 * 16;
    uint32_t ahi0[12][4], ahi1[12][4];
#pragma unroll
    for (int kt = 0; kt < 12; kt++) {
        ldsm4(ahi0[kt], a_base + kt * 32);
        ldsm4(ahi1[kt], a_base + 16 * SAW + kt * 32);
    }
    const int bn  = 8 * (lane >> 4) + (lane & 7);
    const int bk8 = (lane >> 3) & 1;
    const uint32_t bx_b[2] = { sb + BX0 + bn * SX + bk8 * 16, sb + BX1 + bn * SX + bk8 * 16 };
    const uint32_t bh_b[2] = { sb + BH0 + bn * SH + bk8 * 16, sb + BH1 + bn * SH + bk8 * 16 };

    const int cell = 8 * w + (lane >> 2);
    const float* bp = bias + dir * 512;
    const float bi_ = bp[cell]       + bp[256 + cell];
    const float bf_ = bp[64 + cell]  + bp[320 + cell];
    const float bg_ = bp[128 + cell] + bp[384 + cell];
    const float bo_ = bp[192 + cell] + bp[448 + cell];

    float cs[4][2];
#pragma unroll
    for (int nt = 0; nt < 4; nt++) { cs[nt][0] = 0.f; cs[nt][1] = 0.f; }

    float acc[2][4][4];
#pragma unroll
    for (int mt = 0; mt < 2; mt++)
#pragma unroll
        for (int nt = 0; nt < 4; nt++)
#pragma unroll
            for (int r = 0; r < 4; r++) acc[mt][nt][r] = 0.f;

    // prologue: acc = x-part(0)
#pragma unroll
    for (int kt = 0; kt < 8; kt++) {
        uint32_t bx0[4], bx1[4];
        ldsm4(bx0, bx_b[0] + kt * 32);
        ldsm4(bx1, bx_b[0] + 16 * SX + kt * 32);
        mmaf16(acc[0][0], ahi0[kt], bx0);
        mmaf16(acc[0][1], ahi0[kt], bx0 + 2);
        mmaf16(acc[0][2], ahi0[kt], bx1);
        mmaf16(acc[0][3], ahi0[kt], bx1 + 2);
        mmaf16(acc[1][0], ahi1[kt], bx0);
        mmaf16(acc[1][1], ahi1[kt], bx0 + 2);
        mmaf16(acc[1][2], ahi1[kt], bx1);
        mmaf16(acc[1][3], ahi1[kt], bx1 + 2);
    }

    for (int t = 0; t < Lseq; t++) {
        // ---- h-part mma for step t (single pass) — acc entered holding x-part(t) ----
        const uint32_t bh_cur = bh_b[t & 1];
#pragma unroll
        for (int kt = 8; kt < 12; kt++) {
            const int kh = kt - 8;
            uint32_t bh0[4], bh1[4];
            ldsm4(bh0, bh_cur + kh * 32);
            ldsm4(bh1, bh_cur + 16 * SH + kh * 32);
            mmaf16(acc[0][0], ahi0[kt], bh0);
            mmaf16(acc[0][1], ahi0[kt], bh0 + 2);
            mmaf16(acc[0][2], ahi0[kt], bh1);
            mmaf16(acc[0][3], ahi0[kt], bh1 + 2);
            mmaf16(acc[1][0], ahi1[kt], bh0);
            mmaf16(acc[1][1], ahi1[kt], bh0 + 2);
            mmaf16(acc[1][2], ahi1[kt], bh1);
            mmaf16(acc[1][3], ahi1[kt], bh1 + 2);
        }

        // ---- prefetch x(t+2) into registers ----
        uint4 pf0, pf1;
        const bool havepf = (t < Lseq - 2);
        if (havepf) {
            int tn = dir ? (Lseq - 3 - t) : (t + 2);
            pf0 = *(const uint4*)(g_y0 + ((size_t)tn * Bsz + b0i + r0) * 128 + c0 * 8);
            pf1 = *(const uint4*)(g_y0 + ((size_t)tn * Bsz + b0i + r1) * 128 + c0 * 8);
        }

        // ---- epilogue for step t (consumes acc; acc dead after) ----
        const uint32_t bhw = (t & 1) ? BH0 : BH1;
#pragma unroll
        for (int nt = 0; nt < 4; nt++)
#pragma unroll
            for (int hh = 0; hh < 2; hh++) {
                int bb = 8 * nt + 2 * (lane & 3) + hh;
                float iv = acc[0][nt][hh]     + bi_;
                float fv = acc[0][nt][2 + hh] + bf_;
                float gv = acc[1][nt][hh]     + bg_;
                float ov = acc[1][nt][2 + hh] + bo_;
                float c = sigf(fv) * cs[nt][hh] + sigf(iv) * tanha(gv);
                cs[nt][hh] = c;
                float h = sigf(ov) * tanha(c);
                *(__half*)(smem + bhw + bb * SH + cell * 2) = __float2half_rn(h);
                if (t == Lseq - 1)
                    g_hfin[(b0i + bb) * 128 + dir * 64 + cell] = h;
            }

        // ---- x-part mma for step t+1 (reuses acc; overlaps MUFU via warp slip) ----
#pragma unroll
        for (int mt = 0; mt < 2; mt++)
#pragma unroll
            for (int nt = 0; nt < 4; nt++)
#pragma unroll
                for (int r = 0; r < 4; r++) acc[mt][nt][r] = 0.f;
        if (t + 1 < Lseq) {
            const uint32_t bx_cur = bx_b[(t + 1) & 1];
#pragma unroll
            for (int kt = 0; kt < 8; kt++) {
                uint32_t bx0[4], bx1[4];
                ldsm4(bx0, bx_cur + kt * 32);
                ldsm4(bx1, bx_cur + 16 * SX + kt * 32);
                mmaf16(acc[0][0], ahi0[kt], bx0);
                mmaf16(acc[0][1], ahi0[kt], bx0 + 2);
                mmaf16(acc[0][2], ahi0[kt], bx1);
                mmaf16(acc[0][3], ahi0[kt], bx1 + 2);
                mmaf16(acc[1][0], ahi1[kt], bx0);
                mmaf16(acc[1][1], ahi1[kt], bx0 + 2);
                mmaf16(acc[1][2], ahi1[kt], bx1);
                mmaf16(acc[1][3], ahi1[kt], bx1 + 2);
            }
        }

        // ---- store prefetched x(t+2) into the buffer x-mma(t) vacated ----
        if (havepf) {
            const uint32_t bxw = (t & 1) ? BX1 : BX0;
            *(uint4*)(smem + bxw + r0 * SX + c0 * 16) = pf0;
            *(uint4*)(smem + bxw + r1 * SX + c0 * 16) = pf1;
        }
        __syncthreads();   // h(t) + x(t+2) visible
    }
}

// ================= kernel 4: MLP head =================
__global__ void __launch_bounds__(256)
head_kernel(const float* __restrict__ W1, const float* __restrict__ bf1,
            const float* __restrict__ W2, const float* __restrict__ bf2,
            float* __restrict__ out) {
    extern __shared__ float hs[];
    float* sW1 = hs;                           // [64][129]
    float* sh  = hs + 64 * 129;                // [32][129]
    float* sW2 = hs + 64 * 129 + 32 * 129;     // [64]
    float* sb1 = sW2 + 64;                     // [64]
    const int tid = threadIdx.x;
    const int b0 = blockIdx.x * 32;

    for (int i = tid; i < 64 * 128; i += 256) sW1[(i >> 7) * 129 + (i & 127)] = W1[i];
    for (int i = tid; i < 32 * 128; i += 256) sh[(i >> 7) * 129 + (i & 127)] = g_hfin[b0 * 128 + i];
    if (tid < 64) { sW2[tid] = W2[tid]; sb1[tid] = bf1[tid]; }
    __syncthreads();

    const int bi = tid >> 3, g8 = tid & 7;
    const float* hrow = sh + bi * 129;
    float part = 0.f;
#pragma unroll
    for (int jj = 0; jj < 8; jj++) {
        int j = g8 * 8 + jj;
        float z = sb1[j];
        const float* wrow = sW1 + j * 129;
#pragma unroll 16
        for (int k = 0; k < 128; k++) z += hrow[k] * wrow[k];
        part += fmaxf(z, 0.f) * sW2[j];
    }
#pragma unroll
    for (int o = 4; o; o >>= 1) part += __shfl_down_sync(0xffffffffu, part, o, 8);
    if (g8 == 0) out[b0 + bi] = part + bf2[0];
}

// ================= launch =================
extern "C" void kernel_launch(void* const* d_in, const int* in_sizes, int n_in,
                              void* d_out, int out_size) {
    const int*   x    = (const int*)  d_in[0];
    const float* emb  = (const float*)d_in[1];
    const float* Wih0 = (const float*)d_in[2];
    const float* Whh0 = (const float*)d_in[3];
    const float* b0   = (const float*)d_in[4];
    const float* Wih1 = (const float*)d_in[5];
    const float* Whh1 = (const float*)d_in[6];
    const float* b1   = (const float*)d_in[7];
    const float* W1   = (const float*)d_in[8];
    const float* bf1  = (const float*)d_in[9];
    const float* W2   = (const float*)d_in[10];
    const float* bf2  = (const float*)d_in[11];
    float* out = (float*)d_out;

    const int SM0 = 2 * 256 * 144 + 2 * 16 * 144;                 // 78336
    const int SM1 = 256 * 400 + 2 * 32 * 272 + 2 * 32 * 144;      // 129024
    const int SMH = (64 * 129 + 32 * 129 + 128) * 4;
    cudaFuncSetAttribute(lstm0_kernel, cudaFuncAttributeMaxDynamicSharedMemorySize, SM0);
    cudaFuncSetAttribute(lstm1_kernel, cudaFuncAttributeMaxDynamicSharedMemorySize, SM1);
    cudaFuncSetAttribute(head_kernel,  cudaFuncAttributeMaxDynamicSharedMemorySize, SMH);

    table_kernel<<<dim3(128, 2), 256>>>(emb, Wih0, b0);
    lstm0_kernel<<<dim3(Bsz / 16, 2), 256, SM0>>>(x, Whh0);
    lstm1_kernel<<<dim3(Bsz / 32, 2), 256, SM1>>>(Wih1, Whh1, b1);
    head_kernel<<<64, 256, SMH>>>(W1, bf1, W2, bf2, out);
}

// round 15
// speedup vs baseline: 6.7937x; 1.0491x over previous
#include <cuda_runtime.h>
#include <cuda_fp16.h>
#include <cstdint>

#define Bsz   2048
#define Lseq  256

// ---------------- device scratch ----------------
__device__ float g_T0[2 * 128 * 256];                 // token table [dir][tok][cell][gate4] fp32
__device__ __half g_y0[(size_t)Lseq * Bsz * 128];     // layer-0 output fp16 [t][b][128]
__device__ float g_hfin[Bsz * 128];                   // layer-1 final hidden [b][hf|hb]

// ---------------- helpers ----------------
__device__ __forceinline__ uint32_t s2u(const void* p) {
    uint32_t a;
    asm("{ .reg .u64 t; cvta.to.shared.u64 t, %1; cvt.u32.u64 %0, t; }" : "=r"(a) : "l"(p));
    return a;
}
__device__ __forceinline__ float tanha(float x) {
    float y; asm("tanh.approx.f32 %0, %1;" : "=f"(y) : "f"(x)); return y;
}
__device__ __forceinline__ float sigf(float x) { return fmaf(0.5f, tanha(0.5f * x), 0.5f); }

__device__ __forceinline__ void ldsm4(uint32_t* r, uint32_t addr) {
    asm volatile("ldmatrix.sync.aligned.m8n8.x4.shared.b16 {%0,%1,%2,%3}, [%4];"
        : "=r"(r[0]), "=r"(r[1]), "=r"(r[2]), "=r"(r[3]) : "r"(addr));
}
__device__ __forceinline__ void mmaf16(float* d, const uint32_t* a, const uint32_t* b) {
    asm volatile("mma.sync.aligned.m16n8k16.row.col.f32.f16.f16.f32 "
        "{%0,%1,%2,%3}, {%4,%5,%6,%7}, {%8,%9}, {%0,%1,%2,%3};"
        : "+f"(d[0]), "+f"(d[1]), "+f"(d[2]), "+f"(d[3])
        : "r"(a[0]), "r"(a[1]), "r"(a[2]), "r"(a[3]), "r"(b[0]), "r"(b[1]));
}
__device__ __forceinline__ void split2h(float v, __half& hi, __half& lo) {
    hi = __float2half_rn(v);
    lo = __float2half_rn(v - __half2float(hi));
}

// ================= kernel 1: layer-0 token table (fp32 exact) =================
__global__ void table_kernel(const float* __restrict__ emb,
                             const float* __restrict__ Wih0,
                             const float* __restrict__ b0) {
    const int v = blockIdx.x, dir = blockIdx.y, tid = threadIdx.x;
    const int cell = tid >> 2, gate = tid & 3;
    __shared__ float se[64];
    if (tid < 64) se[tid] = emb[v * 64 + tid];
    __syncthreads();
    const float* wrow = Wih0 + (size_t)(dir * 256 + gate * 64 + cell) * 64;
    float s = b0[dir * 512 + gate * 64 + cell] + b0[dir * 512 + 256 + gate * 64 + cell];
#pragma unroll
    for (int k = 0; k < 64; k++) s += se[k] * wrow[k];
    g_T0[((size_t)(dir * 128 + v) * 64 + cell) * 4 + gate] = s;
}

// ================= kernel 2: layer-0 LSTM (unchanged; proven r13/r14) =================
__global__ void __launch_bounds__(256, 2)
lstm0_kernel(const int* __restrict__ xtok, const float* __restrict__ Whh0) {
    constexpr int SA  = 144;
    constexpr int ALO = 256 * SA;
    constexpr int BH0 = 2 * 256 * SA;
    constexpr int BH1 = BH0 + 16 * SA;
    extern __shared__ __align__(16) char smem[];
    const uint32_t sb = s2u(smem);
    const int dir = blockIdx.y, b0i = blockIdx.x * 16;
    const int tid = threadIdx.x, lane = tid & 31, w = tid >> 5;

    {
        const int m = tid;
        const int cellm = 8 * (m >> 5) + (m & 7), gate = (m >> 3) & 3;
        const float* sh = Whh0 + (size_t)(dir * 256 + gate * 64 + cellm) * 64;
        char* rowp = smem + m * SA;
#pragma unroll 8
        for (int k = 0; k < 64; k++) {
            __half hi, lo; split2h(sh[k], hi, lo);
            *(__half*)(rowp + k * 2) = hi;
            *(__half*)(rowp + ALO + k * 2) = lo;
        }
    }
    if (tid < 128) {
        int row = tid >> 3, ch = tid & 7;
        *(uint4*)(smem + BH0 + row * SA + ch * 16) = make_uint4(0, 0, 0, 0);
    }
    __syncthreads();

    const int lrow = ((lane >> 3) & 1) * 8 + (lane & 7);
    const int lk8 = lane >> 4;
    const uint32_t a_base = sb + (32 * w + lrow) * SA + lk8 * 16;
    const uint32_t alo_base = a_base + ALO;
    uint32_t ahi0[4][4], ahi1[4][4];
#pragma unroll
    for (int kt = 0; kt < 4; kt++) {
        ldsm4(ahi0[kt], a_base + kt * 32);
        ldsm4(ahi1[kt], a_base + 16 * SA + kt * 32);
    }
    const int bn = 8 * (lane >> 4) + (lane & 7), bk8 = (lane >> 3) & 1;
    const uint32_t bh_base0 = sb + BH0 + bn * SA + bk8 * 16;
    const uint32_t bh_base1 = sb + BH1 + bn * SA + bk8 * 16;

    const int cell = 8 * w + (lane >> 2);
    float cs[2][2];
    cs[0][0] = cs[0][1] = cs[1][0] = cs[1][1] = 0.f;
    const int srow = (tid >> 3) & 15, sch = tid & 7;
    const float* T0 = g_T0 + (size_t)dir * 128 * 256;

    for (int t = 0; t < Lseq; t++) {
        const int tcur = dir ? (Lseq - 1 - t) : t;
        const uint32_t bh_cur = (t & 1) ? bh_base1 : bh_base0;
        const uint32_t bwofs  = (t & 1) ? BH0 : BH1;

        if (t > 0 && tid < 128) {
            int tprev = dir ? (Lseq - t) : (t - 1);
            uint32_t rofs = ((t & 1) ? BH1 : BH0) + srow * SA + sch * 16;
            *(uint4*)(g_y0 + ((size_t)tprev * Bsz + b0i + srow) * 128 + dir * 64 + sch * 8)
                = *(uint4*)(smem + rofs);
        }

        float4 tv[2][2];
#pragma unroll
        for (int nt = 0; nt < 2; nt++)
#pragma unroll
            for (int hh = 0; hh < 2; hh++) {
                int bb = 8 * nt + 2 * (lane & 3) + hh;
                int tok = __ldg(&xtok[(b0i + bb) * Lseq + tcur]);
                tv[nt][hh] = *(const float4*)(T0 + ((size_t)tok * 64 + cell) * 4);
            }

        float acc[2][2][4];
#pragma unroll
        for (int mt = 0; mt < 2; mt++)
#pragma unroll
            for (int nt = 0; nt < 2; nt++)
#pragma unroll
                for (int r = 0; r < 4; r++) acc[mt][nt][r] = 0.f;
#pragma unroll
        for (int kt = 0; kt < 4; kt++) {
            uint32_t alo0[4], alo1[4], bh0[4];
            ldsm4(alo0, alo_base + kt * 32);
            ldsm4(alo1, alo_base + 16 * SA + kt * 32);
            ldsm4(bh0, bh_cur + kt * 32);
            mmaf16(acc[0][0], ahi0[kt], bh0);     mmaf16(acc[0][0], alo0, bh0);
            mmaf16(acc[0][1], ahi0[kt], bh0 + 2); mmaf16(acc[0][1], alo0, bh0 + 2);
            mmaf16(acc[1][0], ahi1[kt], bh0);     mmaf16(acc[1][0], alo1, bh0);
            mmaf16(acc[1][1], ahi1[kt], bh0 + 2); mmaf16(acc[1][1], alo1, bh0 + 2);
        }

#pragma unroll
        for (int nt = 0; nt < 2; nt++)
#pragma unroll
            for (int hh = 0; hh < 2; hh++) {
                float iv = acc[0][nt][hh]     + tv[nt][hh].x;
                float fv = acc[0][nt][2 + hh] + tv[nt][hh].y;
                float gv = acc[1][nt][hh]     + tv[nt][hh].z;
                float ov = acc[1][nt][2 + hh] + tv[nt][hh].w;
                float c = sigf(fv) * cs[nt][hh] + sigf(iv) * tanha(gv);
                cs[nt][hh] = c;
                float h = sigf(ov) * tanha(c);
                int bb = 8 * nt + 2 * (lane & 3) + hh;
                *(__half*)(smem + bwofs + bb * SA + cell * 2) = __float2half_rn(h);
            }
        __syncthreads();
    }
    if (tid < 128) {
        int tprev = dir ? 0 : (Lseq - 1);
        *(uint4*)(g_y0 + ((size_t)tprev * Bsz + b0i + srow) * 128 + dir * 64 + sch * 8)
            = *(uint4*)(smem + BH0 + srow * SA + sch * 16);
    }
}

// ================= kernel 3: layer-1 LSTM =================
// NB=32, weights fp16 hi-only. DUAL accumulator: per step the in-warp order is
// h-mma(t) -> x-mma(t+1) (into other acc) -> MUFU epilogue(t), so tensor issues
// form one block and the MUFU overlaps the other warp's tensor work.
#define LSTM1_ZACC(A)                                                          \
    do {                                                                       \
        _Pragma("unroll")                                                      \
        for (int mt = 0; mt < 2; mt++)                                         \
            _Pragma("unroll")                                                  \
            for (int nt = 0; nt < 4; nt++)                                     \
                _Pragma("unroll")                                              \
                for (int r = 0; r < 4; r++) A[mt][nt][r] = 0.f;                \
    } while (0)

#define LSTM1_XMMA(A, BXCUR)                                                   \
    do {                                                                       \
        _Pragma("unroll")                                                      \
        for (int kt = 0; kt < 8; kt++) {                                       \
            uint32_t bx0[4], bx1[4];                                           \
            ldsm4(bx0, (BXCUR) + kt * 32);                                     \
            ldsm4(bx1, (BXCUR) + 16 * SX + kt * 32);                           \
            mmaf16(A[0][0], ahi0[kt], bx0);                                    \
            mmaf16(A[0][1], ahi0[kt], bx0 + 2);                                \
            mmaf16(A[0][2], ahi0[kt], bx1);                                    \
            mmaf16(A[0][3], ahi0[kt], bx1 + 2);                                \
            mmaf16(A[1][0], ahi1[kt], bx0);                                    \
            mmaf16(A[1][1], ahi1[kt], bx0 + 2);                                \
            mmaf16(A[1][2], ahi1[kt], bx1);                                    \
            mmaf16(A[1][3], ahi1[kt], bx1 + 2);                                \
        }                                                                      \
    } while (0)

#define LSTM1_HMMA(A, BHCUR)                                                   \
    do {                                                                       \
        _Pragma("unroll")                                                      \
        for (int kh = 0; kh < 4; kh++) {                                       \
            uint32_t bh0[4], bh1[4];                                           \
            ldsm4(bh0, (BHCUR) + kh * 32);                                     \
            ldsm4(bh1, (BHCUR) + 16 * SH + kh * 32);                           \
            mmaf16(A[0][0], ahi0[8 + kh], bh0);                                \
            mmaf16(A[0][1], ahi0[8 + kh], bh0 + 2);                            \
            mmaf16(A[0][2], ahi0[8 + kh], bh1);                                \
            mmaf16(A[0][3], ahi0[8 + kh], bh1 + 2);                            \
            mmaf16(A[1][0], ahi1[8 + kh], bh0);                                \
            mmaf16(A[1][1], ahi1[8 + kh], bh0 + 2);                            \
            mmaf16(A[1][2], ahi1[8 + kh], bh1);                                \
            mmaf16(A[1][3], ahi1[8 + kh], bh1 + 2);                            \
        }                                                                      \
    } while (0)

#define LSTM1_EPILOG(A, T, BHW)                                                \
    do {                                                                       \
        _Pragma("unroll")                                                      \
        for (int nt = 0; nt < 4; nt++)                                         \
            _Pragma("unroll")                                                  \
            for (int hh = 0; hh < 2; hh++) {                                   \
                int bb = 8 * nt + 2 * (lane & 3) + hh;                         \
                float iv = A[0][nt][hh]     + bi_;                             \
                float fv = A[0][nt][2 + hh] + bf_;                             \
                float gv = A[1][nt][hh]     + bg_;                             \
                float ov = A[1][nt][2 + hh] + bo_;                             \
                float c = sigf(fv) * cs[nt][hh] + sigf(iv) * tanha(gv);        \
                cs[nt][hh] = c;                                                \
                float h = sigf(ov) * tanha(c);                                 \
                *(__half*)(smem + (BHW) + bb * SH + cell * 2) = __float2half_rn(h); \
                if ((T) == Lseq - 1)                                           \
                    g_hfin[(b0i + bb) * 128 + dir * 64 + cell] = h;            \
            }                                                                  \
    } while (0)

__global__ void __launch_bounds__(256, 1)
lstm1_kernel(const float* __restrict__ Wih1, const float* __restrict__ Whh1,
             const float* __restrict__ bias) {
    constexpr int SAW = 400;                  // A row stride (192*2+16)
    constexpr int SH  = 144;                  // h row stride
    constexpr int SX  = 272;                  // x row stride
    constexpr int BX0 = 256 * SAW;            // 102400
    constexpr int BX1 = BX0 + 32 * SX;        // 111104
    constexpr int BH0 = BX1 + 32 * SX;        // 119808
    constexpr int BH1 = BH0 + 32 * SH;        // 124416 (total 129024)

    extern __shared__ __align__(16) char smem[];
    const uint32_t sb = s2u(smem);
    const int dir = blockIdx.y, b0i = blockIdx.x * 32;
    const int tid = threadIdx.x, lane = tid & 31, w = tid >> 5;

    // fill weights (hi only), permuted rows
    {
        const int m = tid;
        const int cellm = 8 * (m >> 5) + (m & 7), gate = (m >> 3) & 3;
        const int grow = dir * 256 + gate * 64 + cellm;
        const float* si = Wih1 + (size_t)grow * 128;
        const float* sh = Whh1 + (size_t)grow * 64;
        char* rowp = smem + m * SAW;
        for (int k = 0; k < 128; k++)
            *(__half*)(rowp + k * 2) = __float2half_rn(si[k]);
#pragma unroll 8
        for (int k = 0; k < 64; k++)
            *(__half*)(rowp + (128 + k) * 2) = __float2half_rn(sh[k]);
    }
    { // zero h buffer 0
        int row = tid >> 3, ch = tid & 7;
        *(uint4*)(smem + BH0 + row * SH + ch * 16) = make_uint4(0, 0, 0, 0);
    }
    // stage x(0) -> BX0, x(1) -> BX1
    const int r0 = tid >> 4, c0 = tid & 15, r1 = r0 + 16;
    {
        int t0n = dir ? (Lseq - 1) : 0;
        int t1n = dir ? (Lseq - 2) : 1;
        *(uint4*)(smem + BX0 + r0 * SX + c0 * 16)
            = *(const uint4*)(g_y0 + ((size_t)t0n * Bsz + b0i + r0) * 128 + c0 * 8);
        *(uint4*)(smem + BX0 + r1 * SX + c0 * 16)
            = *(const uint4*)(g_y0 + ((size_t)t0n * Bsz + b0i + r1) * 128 + c0 * 8);
        *(uint4*)(smem + BX1 + r0 * SX + c0 * 16)
            = *(const uint4*)(g_y0 + ((size_t)t1n * Bsz + b0i + r0) * 128 + c0 * 8);
        *(uint4*)(smem + BX1 + r1 * SX + c0 * 16)
            = *(const uint4*)(g_y0 + ((size_t)t1n * Bsz + b0i + r1) * 128 + c0 * 8);
    }
    __syncthreads();

    // A fragments -> registers (12 kt covering K=192)
    const int lrow = ((lane >> 3) & 1) * 8 + (lane & 7);
    const int lk8  = lane >> 4;
    const uint32_t a_base = sb + (32 * w + lrow) * SAW + lk8 * 16;
    uint32_t ahi0[12][4], ahi1[12][4];
#pragma unroll
    for (int kt = 0; kt < 12; kt++) {
        ldsm4(ahi0[kt], a_base + kt * 32);
        ldsm4(ahi1[kt], a_base + 16 * SAW + kt * 32);
    }
    const int bn  = 8 * (lane >> 4) + (lane & 7);
    const int bk8 = (lane >> 3) & 1;
    const uint32_t bxf0 = sb + BX0 + bn * SX + bk8 * 16;
    const uint32_t bxf1 = sb + BX1 + bn * SX + bk8 * 16;
    const uint32_t bhf0 = sb + BH0 + bn * SH + bk8 * 16;
    const uint32_t bhf1 = sb + BH1 + bn * SH + bk8 * 16;

    const int cell = 8 * w + (lane >> 2);
    const float* bp = bias + dir * 512;
    const float bi_ = bp[cell]       + bp[256 + cell];
    const float bf_ = bp[64 + cell]  + bp[320 + cell];
    const float bg_ = bp[128 + cell] + bp[384 + cell];
    const float bo_ = bp[192 + cell] + bp[448 + cell];

    float cs[4][2];
#pragma unroll
    for (int nt = 0; nt < 4; nt++) { cs[nt][0] = 0.f; cs[nt][1] = 0.f; }

    float accA[2][4][4], accB[2][4][4];
    LSTM1_ZACC(accA);
    LSTM1_XMMA(accA, bxf0);    // x-part of step 0

    for (int t = 0; t < Lseq; t += 2) {
        // ---------- step t (even): cur = accA, next = accB ----------
        LSTM1_HMMA(accA, bhf0);                 // h(t-1) in BH0 for even t
        LSTM1_ZACC(accB);
        LSTM1_XMMA(accB, bxf1);                 // x-part of step t+1
        uint4 pf0, pf1;
        bool hp = (t + 2 < Lseq);
        if (hp) {
            int tn = dir ? (Lseq - 3 - t) : (t + 2);
            pf0 = *(const uint4*)(g_y0 + ((size_t)tn * Bsz + b0i + r0) * 128 + c0 * 8);
            pf1 = *(const uint4*)(g_y0 + ((size_t)tn * Bsz + b0i + r1) * 128 + c0 * 8);
        }
        LSTM1_EPILOG(accA, t, BH1);             // h(t) -> BH1
        if (hp) {
            *(uint4*)(smem + BX0 + r0 * SX + c0 * 16) = pf0;   // x(t+2) -> BX0
            *(uint4*)(smem + BX0 + r1 * SX + c0 * 16) = pf1;
        }
        __syncthreads();

        // ---------- step t+1 (odd): cur = accB, next = accA ----------
        LSTM1_HMMA(accB, bhf1);                 // h(t) in BH1
        LSTM1_ZACC(accA);
        if (hp) LSTM1_XMMA(accA, bxf0);         // x-part of step t+2
        uint4 qf0, qf1;
        bool hq = (t + 3 < Lseq);
        if (hq) {
            int tn = dir ? (Lseq - 4 - t) : (t + 3);
            qf0 = *(const uint4*)(g_y0 + ((size_t)tn * Bsz + b0i + r0) * 128 + c0 * 8);
            qf1 = *(const uint4*)(g_y0 + ((size_t)tn * Bsz + b0i + r1) * 128 + c0 * 8);
        }
        LSTM1_EPILOG(accB, t + 1, BH0);         // h(t+1) -> BH0
        if (hq) {
            *(uint4*)(smem + BX1 + r0 * SX + c0 * 16) = qf0;   // x(t+3) -> BX1
            *(uint4*)(smem + BX1 + r1 * SX + c0 * 16) = qf1;
        }
        __syncthreads();
    }
}

// ================= kernel 4: MLP head =================
__global__ void __launch_bounds__(256)
head_kernel(const float* __restrict__ W1, const float* __restrict__ bf1,
            const float* __restrict__ W2, const float* __restrict__ bf2,
            float* __restrict__ out) {
    extern __shared__ float hs[];
    float* sW1 = hs;                           // [64][129]
    float* sh  = hs + 64 * 129;                // [32][129]
    float* sW2 = hs + 64 * 129 + 32 * 129;     // [64]
    float* sb1 = sW2 + 64;                     // [64]
    const int tid = threadIdx.x;
    const int b0 = blockIdx.x * 32;

    for (int i = tid; i < 64 * 128; i += 256) sW1[(i >> 7) * 129 + (i & 127)] = W1[i];
    for (int i = tid; i < 32 * 128; i += 256) sh[(i >> 7) * 129 + (i & 127)] = g_hfin[b0 * 128 + i];
    if (tid < 64) { sW2[tid] = W2[tid]; sb1[tid] = bf1[tid]; }
    __syncthreads();

    const int bi = tid >> 3, g8 = tid & 7;
    const float* hrow = sh + bi * 129;
    float part = 0.f;
#pragma unroll
    for (int jj = 0; jj < 8; jj++) {
        int j = g8 * 8 + jj;
        float z = sb1[j];
        const float* wrow = sW1 + j * 129;
#pragma unroll 16
        for (int k = 0; k < 128; k++) z += hrow[k] * wrow[k];
        part += fmaxf(z, 0.f) * sW2[j];
    }
#pragma unroll
    for (int o = 4; o; o >>= 1) part += __shfl_down_sync(0xffffffffu, part, o, 8);
    if (g8 == 0) out[b0 + bi] = part + bf2[0];
}

// ================= launch =================
extern "C" void kernel_launch(void* const* d_in, const int* in_sizes, int n_in,
                              void* d_out, int out_size) {
    const int*   x    = (const int*)  d_in[0];
    const float* emb  = (const float*)d_in[1];
    const float* Wih0 = (const float*)d_in[2];
    const float* Whh0 = (const float*)d_in[3];
    const float* b0   = (const float*)d_in[4];
    const float* Wih1 = (const float*)d_in[5];
    const float* Whh1 = (const float*)d_in[6];
    const float* b1   = (const float*)d_in[7];
    const float* W1   = (const float*)d_in[8];
    const float* bf1  = (const float*)d_in[9];
    const float* W2   = (const float*)d_in[10];
    const float* bf2  = (const float*)d_in[11];
    float* out = (float*)d_out;

    const int SM0 = 2 * 256 * 144 + 2 * 16 * 144;                 // 78336
    const int SM1 = 256 * 400 + 2 * 32 * 272 + 2 * 32 * 144;      // 129024
    const int SMH = (64 * 129 + 32 * 129 + 128) * 4;
    cudaFuncSetAttribute(lstm0_kernel, cudaFuncAttributeMaxDynamicSharedMemorySize, SM0);
    cudaFuncSetAttribute(lstm1_kernel, cudaFuncAttributeMaxDynamicSharedMemorySize, SM1);
    cudaFuncSetAttribute(head_kernel,  cudaFuncAttributeMaxDynamicSharedMemorySize, SMH);

    table_kernel<<<dim3(128, 2), 256>>>(emb, Wih0, b0);
    lstm0_kernel<<<dim3(Bsz / 16, 2), 256, SM0>>>(x, Whh0);
    lstm1_kernel<<<dim3(Bsz / 32, 2), 256, SM1>>>(Wih1, Whh1, b1);
    head_kernel<<<64, 256, SMH>>>(W1, bf1, W2, bf2, out);
}